// round 1
// baseline (speedup 1.0000x reference)
#include <cuda_runtime.h>
#include <math.h>

#define NN 585
#define BATCH 256
#define INД 512
#define MEM 256
#define ROWS (NN * BATCH)  // 149760

// ---------------- scratch (static device globals; no allocation) ----------------
__device__ float g_P[(size_t)ROWS * 1024];          // [x@Wioux^T + bioux + biouh | x@Wfx^T + bfx]
__device__ float g_c[(size_t)NN * BATCH * MEM];     // c_all
__device__ float g_hsum[64 * BATCH * MEM];          // weighted child-h sum (max level)
__device__ float g_S[(size_t)64 * BATCH * 768];     // hsum @ Wiouh^T
__device__ float g_HW[(size_t)512 * BATCH * MEM];   // weighted child h (per child)
__device__ float g_F[(size_t)512 * BATCH * MEM];    // hw @ Wfh^T + bfh
__device__ float g_Wc[1024 * 512];                  // packed [Wioux; Wfx]
__device__ float g_bc[1024];                        // packed bias

__device__ __forceinline__ float sigf(float x) { return 1.f / (1.f + expf(-x)); }

// ---------------- pack combined weight/bias ----------------
__global__ void pack_wc(const float* __restrict__ Wioux, const float* __restrict__ bioux,
                        const float* __restrict__ biouh, const float* __restrict__ Wfx,
                        const float* __restrict__ bfx) {
    int idx = blockIdx.x * blockDim.x + threadIdx.x;   // 1024*512
    int r = idx >> 9;
    int col = idx & 511;
    g_Wc[idx] = (r < 768) ? Wioux[r * 512 + col] : Wfx[(r - 768) * 512 + col];
    if (col == 0)
        g_bc[r] = (r < 768) ? (bioux[r] + biouh[r]) : bfx[r - 768];
}

// ---------------- SGEMM: C[M,N] = A[M,K] @ B[N,K]^T + bias[N] ----------------
// 128x128 block tile, BK=8, 256 threads, 8x8 per-thread, LDG prefetch.
__global__ __launch_bounds__(256, 2)
void sgemm_nt(const float* __restrict__ A, const float* __restrict__ B,
              const float* __restrict__ bias, float* __restrict__ C,
              int M, int N, int K) {
    __shared__ float As[8][128];
    __shared__ float Bs[8][128];
    const int tid  = threadIdx.x;
    const int bm   = blockIdx.y * 128;
    const int bn   = blockIdx.x * 128;
    const int trow = (tid >> 4) * 8;        // 16 row-groups
    const int tcol = (tid & 15) * 8;        // 16 col-groups
    const int lRow = tid >> 1;              // 0..127
    const int lCol = (tid & 1) * 4;         // 0 or 4

    const float* Ap = A + (long long)(bm + lRow) * K + lCol;
    const float* Bp = B + (long long)(bn + lRow) * K + lCol;

    float acc[8][8];
#pragma unroll
    for (int i = 0; i < 8; i++)
#pragma unroll
        for (int j = 0; j < 8; j++) acc[i][j] = 0.f;

    float4 av = *(const float4*)(Ap);
    float4 bv = *(const float4*)(Bp);

    for (int k0 = 0; k0 < K; k0 += 8) {
        As[lCol + 0][lRow] = av.x; As[lCol + 1][lRow] = av.y;
        As[lCol + 2][lRow] = av.z; As[lCol + 3][lRow] = av.w;
        Bs[lCol + 0][lRow] = bv.x; Bs[lCol + 1][lRow] = bv.y;
        Bs[lCol + 2][lRow] = bv.z; Bs[lCol + 3][lRow] = bv.w;
        __syncthreads();
        if (k0 + 8 < K) {               // prefetch next tile while computing
            av = *(const float4*)(Ap + k0 + 8);
            bv = *(const float4*)(Bp + k0 + 8);
        }
#pragma unroll
        for (int k = 0; k < 8; k++) {
            float4 a0 = *(const float4*)&As[k][trow];
            float4 a1 = *(const float4*)&As[k][trow + 4];
            float4 b0 = *(const float4*)&Bs[k][tcol];
            float4 b1 = *(const float4*)&Bs[k][tcol + 4];
            float ra[8] = {a0.x, a0.y, a0.z, a0.w, a1.x, a1.y, a1.z, a1.w};
            float rb[8] = {b0.x, b0.y, b0.z, b0.w, b1.x, b1.y, b1.z, b1.w};
#pragma unroll
            for (int i = 0; i < 8; i++)
#pragma unroll
                for (int j = 0; j < 8; j++) acc[i][j] += ra[i] * rb[j];
        }
        __syncthreads();
    }

    float bvals[8];
#pragma unroll
    for (int j = 0; j < 8; j++) bvals[j] = bias ? bias[bn + tcol + j] : 0.f;

#pragma unroll
    for (int i = 0; i < 8; i++) {
        long long crow = (long long)(bm + trow + i) * N + bn + tcol;
#pragma unroll
        for (int j = 0; j < 8; j += 4) {
            float4 v;
            v.x = acc[i][j + 0] + bvals[j + 0];
            v.y = acc[i][j + 1] + bvals[j + 1];
            v.z = acc[i][j + 2] + bvals[j + 2];
            v.w = acc[i][j + 3] + bvals[j + 3];
            *(float4*)(C + crow + j) = v;
        }
    }
}

// ---------------- leaves: no children ----------------
__global__ void leaf_act(const float* __restrict__ P, float* __restrict__ c_all,
                         float* __restrict__ h_all) {
    int idx = blockIdx.x * blockDim.x + threadIdx.x;  // 512*256*256
    int m   = idx & 255;
    int rb  = idx >> 8;
    long long row = 73LL * 256 + rb;                  // global (node,batch) row
    const float* p = P + row * 1024;
    float i = sigf(p[m]);
    float o = sigf(p[256 + m]);
    float u = tanhf(p[512 + m]);
    float c = i * u;
    float h = o * tanhf(c);
    c_all[row * 256 + m] = c;
    h_all[row * 256 + m] = h;
}

// ---------------- weighted child h + child-h sum ----------------
__global__ void prep_level(const float* __restrict__ h_all, const float* __restrict__ prob,
                           float* __restrict__ hw, float* __restrict__ hsum, int s) {
    int idx = blockIdx.x * blockDim.x + threadIdx.x;  // L*256*256
    int m  = idx & 255;
    int b  = (idx >> 8) & 255;
    int nl = idx >> 16;
    int n  = s + nl;
    int c0 = n * 8 + 1;
    float sum = 0.f;
#pragma unroll
    for (int j = 0; j < 8; j++) {
        float w  = prob[n * 585 + c0 + j];
        float hv = h_all[((long long)(c0 + j) * 256 + b) * 256 + m];
        float v  = w * hv;
        hw[((long long)((nl * 8 + j) * 256 + b)) * 256 + m] = v;
        sum += v;
    }
    hsum[(long long)idx] = sum;
}

// ---------------- combine: gates + cell update ----------------
__global__ void combine_level(const float* __restrict__ P, const float* __restrict__ S,
                              const float* __restrict__ F, const float* __restrict__ prob,
                              float* __restrict__ c_all, float* __restrict__ h_all, int s) {
    int idx = blockIdx.x * blockDim.x + threadIdx.x;  // L*256*256
    int m  = idx & 255;
    int b  = (idx >> 8) & 255;
    int nl = idx >> 16;
    int n  = s + nl;
    long long prow = (long long)n * 256 + b;
    const float* p  = P + prow * 1024;
    const float* sp = S + (long long)(idx >> 8) * 768;
    float i  = sigf(p[m] + sp[m]);
    float o  = sigf(p[256 + m] + sp[256 + m]);
    float u  = tanhf(p[512 + m] + sp[512 + m]);
    float fx = p[768 + m];
    float c  = i * u;
    int c0 = n * 8 + 1;
#pragma unroll
    for (int j = 0; j < 8; j++) {
        float fpre = F[((long long)((nl * 8 + j) * 256 + b)) * 256 + m];  // has bfh
        float f    = sigf(fpre + fx);
        float w    = prob[n * 585 + c0 + j];
        float cc   = c_all[((long long)(c0 + j) * 256 + b) * 256 + m];
        c += f * (w * cc);
    }
    float h = o * tanhf(c);
    c_all[prow * 256 + m] = c;
    h_all[prow * 256 + m] = h;
}

// ---------------- launch ----------------
extern "C" void kernel_launch(void* const* d_in, const int* in_sizes, int n_in,
                              void* d_out, int out_size) {
    const float* inputs = (const float*)d_in[0];
    const float* prob   = (const float*)d_in[1];
    const float* Wioux  = (const float*)d_in[2];
    const float* bioux  = (const float*)d_in[3];
    const float* Wiouh  = (const float*)d_in[4];
    const float* biouh  = (const float*)d_in[5];
    const float* Wfx    = (const float*)d_in[6];
    const float* bfx    = (const float*)d_in[7];
    const float* Wfh    = (const float*)d_in[8];
    const float* bfh    = (const float*)d_in[9];
    float* h_all = (float*)d_out;

    float *P, *Call, *Hsum, *Sb, *HW, *Fb, *Wc, *bc;
    cudaGetSymbolAddress((void**)&P,    g_P);
    cudaGetSymbolAddress((void**)&Call, g_c);
    cudaGetSymbolAddress((void**)&Hsum, g_hsum);
    cudaGetSymbolAddress((void**)&Sb,   g_S);
    cudaGetSymbolAddress((void**)&HW,   g_HW);
    cudaGetSymbolAddress((void**)&Fb,   g_F);
    cudaGetSymbolAddress((void**)&Wc,   g_Wc);
    cudaGetSymbolAddress((void**)&bc,   g_bc);

    // 1. pack combined weights/bias
    pack_wc<<<(1024 * 512) / 256, 256>>>(Wioux, bioux, biouh, Wfx, bfx);

    // 2. big input projection: P = X @ [Wioux;Wfx]^T + bias   (149760 x 1024 x 512)
    sgemm_nt<<<dim3(1024 / 128, ROWS / 128), 256>>>(inputs, Wc, bc, P, ROWS, 1024, 512);

    // 3. leaves (level 3): 512 nodes
    leaf_act<<<(512 * 256 * 256) / 256, 256>>>(P, Call, h_all);

    // 4. internal levels bottom-up
    const int starts[3] = {9, 1, 0};
    const int sizes[3]  = {64, 8, 1};
    for (int l = 0; l < 3; l++) {
        int s = starts[l], L = sizes[l];
        prep_level<<<(L * 256 * 256) / 256, 256>>>(h_all, prob, HW, Hsum, s);
        // S = hsum @ Wiouh^T                (L*256 x 768 x 256)
        sgemm_nt<<<dim3(768 / 128, (L * 256) / 128), 256>>>(Hsum, Wiouh, nullptr, Sb,
                                                            L * 256, 768, 256);
        // F = hw @ Wfh^T + bfh              (L*8*256 x 256 x 256)
        sgemm_nt<<<dim3(256 / 128, (L * 8 * 256) / 128), 256>>>(HW, Wfh, bfh, Fb,
                                                                L * 8 * 256, 256, 256);
        combine_level<<<(L * 256 * 256) / 256, 256>>>(P, Sb, Fb, prob, Call, h_all, s);
    }
}

// round 3
// speedup vs baseline: 1.8309x; 1.8309x over previous
#include <cuda_runtime.h>
#include <cuda_bf16.h>
#include <math.h>
#include <stdint.h>

#define NN 585
#define BATCH 256
#define MEM 256
#define ROWS (NN * BATCH)  // 149760

// ---------------- scratch (static device globals; no allocation) ----------------
__device__ __align__(128) float g_P[(size_t)ROWS * 1024];        // packed projections
__device__ __align__(128) float g_c[(size_t)NN * BATCH * MEM];   // c_all
__device__ __align__(128) float g_S[(size_t)64 * BATCH * 768];   // hsum @ Wiouh^T
__device__ __align__(128) float g_F[(size_t)512 * BATCH * MEM];  // hw @ Wfh^T + bfh
__device__ __align__(128) float g_bc[1024];                      // packed bias

// bf16 hi/lo split operands
__device__ __align__(128) __nv_bfloat16 g_Ahi[(size_t)ROWS * 512];
__device__ __align__(128) __nv_bfloat16 g_Alo[(size_t)ROWS * 512];
__device__ __align__(128) __nv_bfloat16 g_Wchi[1024 * 512];
__device__ __align__(128) __nv_bfloat16 g_Wclo[1024 * 512];
__device__ __align__(128) __nv_bfloat16 g_Whhi[768 * 256];
__device__ __align__(128) __nv_bfloat16 g_Whlo[768 * 256];
__device__ __align__(128) __nv_bfloat16 g_Wfhi[256 * 256];
__device__ __align__(128) __nv_bfloat16 g_Wflo[256 * 256];
__device__ __align__(128) __nv_bfloat16 g_HShi[64 * BATCH * 256];
__device__ __align__(128) __nv_bfloat16 g_HSlo[64 * BATCH * 256];
__device__ __align__(128) __nv_bfloat16 g_HWhi[(size_t)512 * BATCH * 256];
__device__ __align__(128) __nv_bfloat16 g_HWlo[(size_t)512 * BATCH * 256];

// ---------------- helpers ----------------
__device__ __forceinline__ uint32_t smem_u32(const void* p) {
    uint32_t a;
    asm("{ .reg .u64 t; cvta.to.shared.u64 t, %1; cvt.u32.u64 %0, t; }" : "=r"(a) : "l"(p));
    return a;
}
__device__ __forceinline__ void cpa16(uint32_t dst, const void* src) {
    asm volatile("cp.async.cg.shared.global [%0], [%1], 16;" :: "r"(dst), "l"(src));
}
#define CP_COMMIT() asm volatile("cp.async.commit_group;" ::: "memory")

#define LDSM4(r, addr)                                                                  \
    asm volatile("ldmatrix.sync.aligned.m8n8.x4.shared.b16 {%0,%1,%2,%3}, [%4];"        \
                 : "=r"((r)[0]), "=r"((r)[1]), "=r"((r)[2]), "=r"((r)[3]) : "r"(addr))

#define MMA(c, a, b0, b1)                                                               \
    asm volatile("mma.sync.aligned.m16n8k16.row.col.f32.bf16.bf16.f32 "                 \
                 "{%0,%1,%2,%3},{%4,%5,%6,%7},{%8,%9},{%0,%1,%2,%3};"                   \
                 : "+f"((c)[0]), "+f"((c)[1]), "+f"((c)[2]), "+f"((c)[3])               \
                 : "r"((a)[0]), "r"((a)[1]), "r"((a)[2]), "r"((a)[3]), "r"(b0), "r"(b1))

__device__ __forceinline__ float sigf(float x) { return 1.f / (1.f + expf(-x)); }
__device__ __forceinline__ void split2(float v, __nv_bfloat16& h, __nv_bfloat16& l) {
    h = __float2bfloat16(v);
    l = __float2bfloat16(v - __bfloat162float(h));
}

// ---------------- fp32 -> bf16 hi/lo split (vectorized) ----------------
__global__ void conv_split(const float* __restrict__ x, __nv_bfloat16* __restrict__ hi,
                           __nv_bfloat16* __restrict__ lo, long long n4) {
    long long i = blockIdx.x * (long long)blockDim.x + threadIdx.x;
    if (i >= n4) return;
    float4 v = ((const float4*)x)[i];
    __nv_bfloat16 h0, h1, h2, h3, l0, l1, l2, l3;
    split2(v.x, h0, l0); split2(v.y, h1, l1); split2(v.z, h2, l2); split2(v.w, h3, l3);
    ((__nv_bfloat162*)hi)[i * 2 + 0] = __nv_bfloat162(h0, h1);
    ((__nv_bfloat162*)hi)[i * 2 + 1] = __nv_bfloat162(h2, h3);
    ((__nv_bfloat162*)lo)[i * 2 + 0] = __nv_bfloat162(l0, l1);
    ((__nv_bfloat162*)lo)[i * 2 + 1] = __nv_bfloat162(l2, l3);
}

// ---------------- pack combined weight (split) + bias ----------------
__global__ void pack_wc(const float* __restrict__ Wioux, const float* __restrict__ bioux,
                        const float* __restrict__ biouh, const float* __restrict__ Wfx,
                        const float* __restrict__ bfx) {
    int idx = blockIdx.x * blockDim.x + threadIdx.x;  // 1024*512
    int r = idx >> 9;
    int col = idx & 511;
    float w = (r < 768) ? Wioux[r * 512 + col] : Wfx[(r - 768) * 512 + col];
    split2(w, g_Wchi[idx], g_Wclo[idx]);
    if (col == 0)
        g_bc[r] = (r < 768) ? (bioux[r] + biouh[r]) : bfx[r - 768];
}

// ============ mma.sync bf16x3 GEMM: C[M,N] = A[M,K]@B[N,K]^T (+bias[N]) ============
// 128x128x32 CTA tile, 256 threads (8 warps, 2x4), 4-stage cp.async pipeline.
// smem tiles padded to 80B row stride for conflict-free ldmatrix.
#define TILE_B   10240          // 128 rows * 80B
#define STAGE_B  (4 * TILE_B)   // Ahi, Alo, Bhi, Blo
#define NSTAGE   4
#define GEMM_SMEM (NSTAGE * STAGE_B)

__device__ __forceinline__ void load_stage(uint32_t dst, const __nv_bfloat16* A0,
                                           const __nv_bfloat16* A1, const __nv_bfloat16* B0,
                                           const __nv_bfloat16* B1, int K, int k0, int tid) {
    const __nv_bfloat16* srcs[4] = {A0, A1, B0, B1};
#pragma unroll
    for (int i = 0; i < 8; i++) {
        int chunk = tid + i * 256;       // 0..2047
        int tile = chunk >> 9;
        int w = chunk & 511;
        int row = w >> 2, c = w & 3;
        cpa16(dst + tile * TILE_B + row * 80 + c * 16, srcs[tile] + (size_t)row * K + k0 + c * 8);
    }
    CP_COMMIT();
}

__global__ __launch_bounds__(256, 1)
void tgemm(const __nv_bfloat16* __restrict__ Ahi, const __nv_bfloat16* __restrict__ Alo,
           const __nv_bfloat16* __restrict__ Bhi, const __nv_bfloat16* __restrict__ Blo,
           const float* __restrict__ bias, float* __restrict__ C, int M, int N, int K) {
    extern __shared__ __align__(128) char smem[];
    uint32_t sb = smem_u32(smem);
    const int tid = threadIdx.x;
    const int warp = tid >> 5;
    const int lane = tid & 31;
    const int wm = warp >> 2;       // 0..1
    const int wn = warp & 3;        // 0..3
    const int bn = blockIdx.x * 128;
    const int bm = blockIdx.y * 128;
    const int NK = K >> 5;

    const __nv_bfloat16* A0 = Ahi + (size_t)bm * K;
    const __nv_bfloat16* A1 = Alo + (size_t)bm * K;
    const __nv_bfloat16* B0 = Bhi + (size_t)bn * K;
    const __nv_bfloat16* B1 = Blo + (size_t)bn * K;

    // prologue: fill pipeline (up to NSTAGE-1 stages in flight)
#pragma unroll
    for (int s = 0; s < NSTAGE - 1; s++)
        if (s < NK) load_stage(sb + s * STAGE_B, A0, A1, B0, B1, K, s * 32, tid);

    float acc[4][4][4];
#pragma unroll
    for (int mi = 0; mi < 4; mi++)
#pragma unroll
        for (int ni = 0; ni < 4; ni++)
#pragma unroll
            for (int r = 0; r < 4; r++) acc[mi][ni][r] = 0.f;

    // per-thread ldmatrix base offsets (tile-relative)
    uint32_t aoff[4], boff[2];
#pragma unroll
    for (int mi = 0; mi < 4; mi++)
        aoff[mi] = (uint32_t)((wm * 64 + mi * 16 + (lane & 15)) * 80 + (lane >> 4) * 16);
#pragma unroll
    for (int np = 0; np < 2; np++)
        boff[np] = (uint32_t)((wn * 32 + np * 16 + (lane & 15)) * 80 + (lane >> 4) * 16);

    for (int k = 0; k < NK; k++) {
        int kpre = k + NSTAGE - 1;
        if (kpre < NK)
            load_stage(sb + (kpre % NSTAGE) * STAGE_B, A0, A1, B0, B1, K, kpre * 32, tid);
        // wait until stage k is resident
        int inflight = ((kpre < NK ? kpre : NK - 1)) - k;
        if (inflight >= 3)      asm volatile("cp.async.wait_group 3;" ::: "memory");
        else if (inflight == 2) asm volatile("cp.async.wait_group 2;" ::: "memory");
        else if (inflight == 1) asm volatile("cp.async.wait_group 1;" ::: "memory");
        else                    asm volatile("cp.async.wait_group 0;" ::: "memory");
        __syncthreads();

        uint32_t st = sb + (k % NSTAGE) * STAGE_B;
#pragma unroll
        for (int ks = 0; ks < 2; ks++) {
            uint32_t ko = ks * 32;
            uint32_t ah[4][4], al[4][4], bh[2][4], bl[2][4];
#pragma unroll
            for (int mi = 0; mi < 4; mi++) {
                LDSM4(ah[mi], st + aoff[mi] + ko);
                LDSM4(al[mi], st + TILE_B + aoff[mi] + ko);
            }
#pragma unroll
            for (int np = 0; np < 2; np++) {
                LDSM4(bh[np], st + 2 * TILE_B + boff[np] + ko);
                LDSM4(bl[np], st + 3 * TILE_B + boff[np] + ko);
            }
#pragma unroll
            for (int mi = 0; mi < 4; mi++)
#pragma unroll
                for (int ni = 0; ni < 4; ni++) {
                    int np = ni >> 1, sub = ni & 1;
                    MMA(acc[mi][ni], ah[mi], bh[np][sub], bh[np][sub + 2]);
                    MMA(acc[mi][ni], ah[mi], bl[np][sub], bl[np][sub + 2]);
                    MMA(acc[mi][ni], al[mi], bh[np][sub], bh[np][sub + 2]);
                }
        }
        __syncthreads();   // protect stage reuse by next prefetch
    }

    // epilogue: direct coalesced-ish float2 stores
#pragma unroll
    for (int ni = 0; ni < 4; ni++) {
        int col = bn + wn * 32 + ni * 8 + (lane & 3) * 2;
        float b0 = 0.f, b1 = 0.f;
        if (bias) { b0 = bias[col]; b1 = bias[col + 1]; }
#pragma unroll
        for (int mi = 0; mi < 4; mi++) {
            int row = bm + wm * 64 + mi * 16 + (lane >> 2);
            float2 v0 = make_float2(acc[mi][ni][0] + b0, acc[mi][ni][1] + b1);
            float2 v1 = make_float2(acc[mi][ni][2] + b0, acc[mi][ni][3] + b1);
            *(float2*)(C + (size_t)row * N + col) = v0;
            *(float2*)(C + (size_t)(row + 8) * N + col) = v1;
        }
    }
}

// ---------------- leaves ----------------
__global__ void leaf_act(const float* __restrict__ P, float* __restrict__ c_all,
                         float* __restrict__ h_all) {
    int idx = blockIdx.x * blockDim.x + threadIdx.x;  // 512*256*256
    int m = idx & 255;
    int rb = idx >> 8;
    long long row = 73LL * 256 + rb;
    const float* p = P + row * 1024;
    float i = sigf(p[m]);
    float o = sigf(p[256 + m]);
    float u = tanhf(p[512 + m]);
    float c = i * u;
    float h = o * tanhf(c);
    c_all[row * 256 + m] = c;
    h_all[row * 256 + m] = h;
}

// ---------------- weighted child h (split) + child-h sum (split) ----------------
__global__ void prep_level(const float* __restrict__ h_all, const float* __restrict__ prob,
                           __nv_bfloat16* __restrict__ hwh, __nv_bfloat16* __restrict__ hwl,
                           __nv_bfloat16* __restrict__ hsh, __nv_bfloat16* __restrict__ hsl,
                           int s) {
    int idx = blockIdx.x * blockDim.x + threadIdx.x;  // L*256*256
    int m = idx & 255;
    int b = (idx >> 8) & 255;
    int nl = idx >> 16;
    int n = s + nl;
    int c0 = n * 8 + 1;
    float sum = 0.f;
#pragma unroll
    for (int j = 0; j < 8; j++) {
        float w = prob[n * 585 + c0 + j];
        float hv = h_all[((long long)(c0 + j) * 256 + b) * 256 + m];
        float v = w * hv;
        long long off = ((long long)((nl * 8 + j) * 256 + b)) * 256 + m;
        split2(v, hwh[off], hwl[off]);
        sum += v;
    }
    split2(sum, hsh[idx], hsl[idx]);
}

// ---------------- combine ----------------
__global__ void combine_level(const float* __restrict__ P, const float* __restrict__ S,
                              const float* __restrict__ F, const float* __restrict__ prob,
                              float* __restrict__ c_all, float* __restrict__ h_all, int s) {
    int idx = blockIdx.x * blockDim.x + threadIdx.x;  // L*256*256
    int m = idx & 255;
    int b = (idx >> 8) & 255;
    int nl = idx >> 16;
    int n = s + nl;
    long long prow = (long long)n * 256 + b;
    const float* p = P + prow * 1024;
    const float* sp = S + (long long)(idx >> 8) * 768;
    float i = sigf(p[m] + sp[m]);
    float o = sigf(p[256 + m] + sp[256 + m]);
    float u = tanhf(p[512 + m] + sp[512 + m]);
    float fx = p[768 + m];
    float c = i * u;
    int c0 = n * 8 + 1;
#pragma unroll
    for (int j = 0; j < 8; j++) {
        float fpre = F[((long long)((nl * 8 + j) * 256 + b)) * 256 + m];  // has bfh
        float f = sigf(fpre + fx);
        float w = prob[n * 585 + c0 + j];
        float cc = c_all[((long long)(c0 + j) * 256 + b) * 256 + m];
        c += f * (w * cc);
    }
    float h = o * tanhf(c);
    c_all[prow * 256 + m] = c;
    h_all[prow * 256 + m] = h;
}

// ---------------- launch ----------------
extern "C" void kernel_launch(void* const* d_in, const int* in_sizes, int n_in,
                              void* d_out, int out_size) {
    const float* inputs = (const float*)d_in[0];
    const float* prob = (const float*)d_in[1];
    const float* Wioux = (const float*)d_in[2];
    const float* bioux = (const float*)d_in[3];
    const float* Wiouh = (const float*)d_in[4];
    const float* biouh = (const float*)d_in[5];
    const float* Wfx = (const float*)d_in[6];
    const float* bfx = (const float*)d_in[7];
    const float* Wfh = (const float*)d_in[8];
    const float* bfh = (const float*)d_in[9];
    float* h_all = (float*)d_out;

    float *P, *Call, *Sb, *Fb, *bc;
    __nv_bfloat16 *Ahi, *Alo, *Wchi, *Wclo, *Whhi, *Whlo, *Wfhi, *Wflo;
    __nv_bfloat16 *HShi, *HSlo, *HWhi, *HWlo;
    cudaGetSymbolAddress((void**)&P, g_P);
    cudaGetSymbolAddress((void**)&Call, g_c);
    cudaGetSymbolAddress((void**)&Sb, g_S);
    cudaGetSymbolAddress((void**)&Fb, g_F);
    cudaGetSymbolAddress((void**)&bc, g_bc);
    cudaGetSymbolAddress((void**)&Ahi, g_Ahi);
    cudaGetSymbolAddress((void**)&Alo, g_Alo);
    cudaGetSymbolAddress((void**)&Wchi, g_Wchi);
    cudaGetSymbolAddress((void**)&Wclo, g_Wclo);
    cudaGetSymbolAddress((void**)&Whhi, g_Whhi);
    cudaGetSymbolAddress((void**)&Whlo, g_Whlo);
    cudaGetSymbolAddress((void**)&Wfhi, g_Wfhi);
    cudaGetSymbolAddress((void**)&Wflo, g_Wflo);
    cudaGetSymbolAddress((void**)&HShi, g_HShi);
    cudaGetSymbolAddress((void**)&HSlo, g_HSlo);
    cudaGetSymbolAddress((void**)&HWhi, g_HWhi);
    cudaGetSymbolAddress((void**)&HWlo, g_HWlo);

    cudaFuncSetAttribute(tgemm, cudaFuncAttributeMaxDynamicSharedMemorySize, GEMM_SMEM);

    // conversions / packing
    conv_split<<<(int)((size_t)ROWS * 512 / 4 / 256), 256>>>(inputs, Ahi, Alo,
                                                             (long long)ROWS * 512 / 4);
    pack_wc<<<2048, 256>>>(Wioux, bioux, biouh, Wfx, bfx);
    conv_split<<<192, 256>>>(Wiouh, Whhi, Whlo, 768 * 256 / 4);
    conv_split<<<64, 256>>>(Wfh, Wfhi, Wflo, 256 * 256 / 4);

    // big input projection: P = X @ [Wioux;Wfx]^T + bias   (149760 x 1024 x 512)
    tgemm<<<dim3(8, ROWS / 128), 256, GEMM_SMEM>>>(Ahi, Alo, Wchi, Wclo, bc, P, ROWS, 1024, 512);

    // leaves
    leaf_act<<<(512 * 256 * 256) / 256, 256>>>(P, Call, h_all);

    // internal levels bottom-up
    const int starts[3] = {9, 1, 0};
    const int sizes[3] = {64, 8, 1};
    for (int l = 0; l < 3; l++) {
        int s = starts[l], L = sizes[l];
        prep_level<<<(L * 256 * 256) / 256, 256>>>(h_all, prob, HWhi, HWlo, HShi, HSlo, s);
        // S = hsum @ Wiouh^T   (L*256 x 768 x 256)
        tgemm<<<dim3(6, (L * 256) / 128), 256, GEMM_SMEM>>>(HShi, HSlo, Whhi, Whlo, nullptr, Sb,
                                                            L * 256, 768, 256);
        // F = hw @ Wfh^T + bfh (L*8*256 x 256 x 256)
        tgemm<<<dim3(2, (L * 8 * 256) / 128), 256, GEMM_SMEM>>>(HWhi, HWlo, Wfhi, Wflo, bfh, Fb,
                                                                L * 8 * 256, 256, 256);
        combine_level<<<(L * 256 * 256) / 256, 256>>>(P, Sb, Fb, prob, Call, h_all, s);
    }
}

// round 4
// speedup vs baseline: 1.8880x; 1.0312x over previous
#include <cuda_runtime.h>
#include <cuda_bf16.h>
#include <math.h>
#include <stdint.h>

#define NN 585
#define BATCH 256
#define MEM 256
#define ROWS (NN * BATCH)  // 149760

// ---------------- scratch (static device globals; no allocation) ----------------
__device__ __align__(128) float g_P[(size_t)ROWS * 1024];        // packed projections
__device__ __align__(128) float g_c[(size_t)NN * BATCH * MEM];   // c_all
__device__ __align__(128) float g_S[(size_t)64 * BATCH * 768];   // hsum @ Wiouh^T
__device__ __align__(128) float g_F[(size_t)512 * BATCH * MEM];  // hw @ Wfh^T + bfh
__device__ __align__(128) float g_bc[1024];                      // packed bias

// bf16 hi/lo split operands
__device__ __align__(128) __nv_bfloat16 g_Ahi[(size_t)ROWS * 512];
__device__ __align__(128) __nv_bfloat16 g_Alo[(size_t)ROWS * 512];
__device__ __align__(128) __nv_bfloat16 g_Wchi[1024 * 512];
__device__ __align__(128) __nv_bfloat16 g_Wclo[1024 * 512];
__device__ __align__(128) __nv_bfloat16 g_Whhi[768 * 256];
__device__ __align__(128) __nv_bfloat16 g_Whlo[768 * 256];
__device__ __align__(128) __nv_bfloat16 g_Wfhi[256 * 256];
__device__ __align__(128) __nv_bfloat16 g_Wflo[256 * 256];
__device__ __align__(128) __nv_bfloat16 g_HShi[64 * BATCH * 256];
__device__ __align__(128) __nv_bfloat16 g_HSlo[64 * BATCH * 256];
__device__ __align__(128) __nv_bfloat16 g_HWhi[(size_t)512 * BATCH * 256];
__device__ __align__(128) __nv_bfloat16 g_HWlo[(size_t)512 * BATCH * 256];

// ---------------- helpers ----------------
__device__ __forceinline__ uint32_t smem_u32(const void* p) {
    uint32_t a;
    asm("{ .reg .u64 t; cvta.to.shared.u64 t, %1; cvt.u32.u64 %0, t; }" : "=r"(a) : "l"(p));
    return a;
}
__device__ __forceinline__ void cpa16(uint32_t dst, const void* src) {
    asm volatile("cp.async.cg.shared.global [%0], [%1], 16;" :: "r"(dst), "l"(src));
}
#define CP_COMMIT() asm volatile("cp.async.commit_group;" ::: "memory")

#define LDSM4(r, addr)                                                                  \
    asm volatile("ldmatrix.sync.aligned.m8n8.x4.shared.b16 {%0,%1,%2,%3}, [%4];"        \
                 : "=r"((r)[0]), "=r"((r)[1]), "=r"((r)[2]), "=r"((r)[3]) : "r"(addr))

#define MMA(c, a, b0, b1)                                                               \
    asm volatile("mma.sync.aligned.m16n8k16.row.col.f32.bf16.bf16.f32 "                 \
                 "{%0,%1,%2,%3},{%4,%5,%6,%7},{%8,%9},{%0,%1,%2,%3};"                   \
                 : "+f"((c)[0]), "+f"((c)[1]), "+f"((c)[2]), "+f"((c)[3])               \
                 : "r"((a)[0]), "r"((a)[1]), "r"((a)[2]), "r"((a)[3]), "r"(b0), "r"(b1))

__device__ __forceinline__ float sigf(float x) { return 1.f / (1.f + expf(-x)); }
__device__ __forceinline__ void split2(float v, __nv_bfloat16& h, __nv_bfloat16& l) {
    h = __float2bfloat16(v);
    l = __float2bfloat16(v - __bfloat162float(h));
}

// ---------------- fp32 -> bf16 hi/lo split (vectorized) ----------------
__global__ void conv_split(const float* __restrict__ x, __nv_bfloat16* __restrict__ hi,
                           __nv_bfloat16* __restrict__ lo, long long n4) {
    long long i = blockIdx.x * (long long)blockDim.x + threadIdx.x;
    if (i >= n4) return;
    float4 v = ((const float4*)x)[i];
    __nv_bfloat16 h0, h1, h2, h3, l0, l1, l2, l3;
    split2(v.x, h0, l0); split2(v.y, h1, l1); split2(v.z, h2, l2); split2(v.w, h3, l3);
    ((__nv_bfloat162*)hi)[i * 2 + 0] = __nv_bfloat162(h0, h1);
    ((__nv_bfloat162*)hi)[i * 2 + 1] = __nv_bfloat162(h2, h3);
    ((__nv_bfloat162*)lo)[i * 2 + 0] = __nv_bfloat162(l0, l1);
    ((__nv_bfloat162*)lo)[i * 2 + 1] = __nv_bfloat162(l2, l3);
}

// ---------------- pack combined weight (split) + bias ----------------
__global__ void pack_wc(const float* __restrict__ Wioux, const float* __restrict__ bioux,
                        const float* __restrict__ biouh, const float* __restrict__ Wfx,
                        const float* __restrict__ bfx) {
    int idx = blockIdx.x * blockDim.x + threadIdx.x;  // 1024*512
    int r = idx >> 9;
    int col = idx & 511;
    float w = (r < 768) ? Wioux[r * 512 + col] : Wfx[(r - 768) * 512 + col];
    split2(w, g_Wchi[idx], g_Wclo[idx]);
    if (col == 0)
        g_bc[r] = (r < 768) ? (bioux[r] + biouh[r]) : bfx[r - 768];
}

// ============ mma.sync bf16x3 GEMM: C[M,N] = A[M,K]@B[N,K]^T (+bias[N]) ============
// 128x128x32 CTA tile, 512 threads (16 warps, 4x4), 3-stage cp.async pipeline.
// smem tiles padded to 80B row stride for conflict-free ldmatrix.
#define TILE_B   10240          // 128 rows * 80B
#define STAGE_B  (4 * TILE_B)   // Ahi, Alo, Bhi, Blo
#define NSTAGE   3
#define GEMM_SMEM (NSTAGE * STAGE_B)

__device__ __forceinline__ void load_stage(uint32_t dst, const __nv_bfloat16* A0,
                                           const __nv_bfloat16* A1, const __nv_bfloat16* B0,
                                           const __nv_bfloat16* B1, int K, int k0, int tid) {
    const __nv_bfloat16* srcs[4] = {A0, A1, B0, B1};
#pragma unroll
    for (int i = 0; i < 4; i++) {
        int chunk = tid + i * 512;       // 0..2047
        int tile = chunk >> 9;
        int w = chunk & 511;
        int row = w >> 2, c = w & 3;
        cpa16(dst + tile * TILE_B + row * 80 + c * 16, srcs[tile] + (size_t)row * K + k0 + c * 8);
    }
    CP_COMMIT();
}

// fragment bundle for one ks (K=16) slice per warp (32x32 warp tile)
struct Frag {
    uint32_t ah[2][4], al[2][4], bh[2][4], bl[2][4];
};
__device__ __forceinline__ void load_frag(Frag& f, uint32_t st, const uint32_t* aoff,
                                          const uint32_t* boff, uint32_t ko) {
#pragma unroll
    for (int mi = 0; mi < 2; mi++) {
        LDSM4(f.ah[mi], st + aoff[mi] + ko);
        LDSM4(f.al[mi], st + TILE_B + aoff[mi] + ko);
    }
#pragma unroll
    for (int np = 0; np < 2; np++) {
        LDSM4(f.bh[np], st + 2 * TILE_B + boff[np] + ko);
        LDSM4(f.bl[np], st + 3 * TILE_B + boff[np] + ko);
    }
}
__device__ __forceinline__ void do_mma(float (*acc)[4][4], const Frag& f) {
#pragma unroll
    for (int mi = 0; mi < 2; mi++)
#pragma unroll
        for (int ni = 0; ni < 4; ni++) {
            int np = ni >> 1, sub = ni & 1;
            MMA(acc[mi][ni], f.ah[mi], f.bh[np][sub], f.bh[np][sub + 2]);
            MMA(acc[mi][ni], f.ah[mi], f.bl[np][sub], f.bl[np][sub + 2]);
            MMA(acc[mi][ni], f.al[mi], f.bh[np][sub], f.bh[np][sub + 2]);
        }
}

__global__ __launch_bounds__(512, 1)
void tgemm(const __nv_bfloat16* __restrict__ Ahi, const __nv_bfloat16* __restrict__ Alo,
           const __nv_bfloat16* __restrict__ Bhi, const __nv_bfloat16* __restrict__ Blo,
           const float* __restrict__ bias, float* __restrict__ C, int M, int N, int K) {
    extern __shared__ __align__(128) char smem[];
    uint32_t sb = smem_u32(smem);
    const int tid = threadIdx.x;
    const int warp = tid >> 5;
    const int lane = tid & 31;
    const int wm = warp >> 2;       // 0..3
    const int wn = warp & 3;        // 0..3
    const int bn = blockIdx.x * 128;
    const int bm = blockIdx.y * 128;
    const int NK = K >> 5;

    const __nv_bfloat16* A0 = Ahi + (size_t)bm * K;
    const __nv_bfloat16* A1 = Alo + (size_t)bm * K;
    const __nv_bfloat16* B0 = Bhi + (size_t)bn * K;
    const __nv_bfloat16* B1 = Blo + (size_t)bn * K;

    // prologue: fill pipeline (NSTAGE-1 stages in flight)
#pragma unroll
    for (int s = 0; s < NSTAGE - 1; s++)
        if (s < NK) load_stage(sb + s * STAGE_B, A0, A1, B0, B1, K, s * 32, tid);

    float acc[2][4][4];
#pragma unroll
    for (int mi = 0; mi < 2; mi++)
#pragma unroll
        for (int ni = 0; ni < 4; ni++)
#pragma unroll
            for (int r = 0; r < 4; r++) acc[mi][ni][r] = 0.f;

    // per-thread ldmatrix base offsets (tile-relative), 32x32 warp tile
    uint32_t aoff[2], boff[2];
#pragma unroll
    for (int mi = 0; mi < 2; mi++)
        aoff[mi] = (uint32_t)((wm * 32 + mi * 16 + (lane & 15)) * 80 + (lane >> 4) * 16);
#pragma unroll
    for (int np = 0; np < 2; np++)
        boff[np] = (uint32_t)((wn * 32 + np * 16 + (lane & 15)) * 80 + (lane >> 4) * 16);

    for (int k = 0; k < NK; k++) {
        int kpre = k + NSTAGE - 1;
        if (kpre < NK)
            load_stage(sb + (kpre % NSTAGE) * STAGE_B, A0, A1, B0, B1, K, kpre * 32, tid);
        int inflight = ((kpre < NK ? kpre : NK - 1)) - k;
        if (inflight >= 2)      asm volatile("cp.async.wait_group 2;" ::: "memory");
        else if (inflight == 1) asm volatile("cp.async.wait_group 1;" ::: "memory");
        else                    asm volatile("cp.async.wait_group 0;" ::: "memory");
        __syncthreads();

        uint32_t st = sb + (k % NSTAGE) * STAGE_B;
        Frag f0, f1;
        load_frag(f0, st, aoff, boff, 0);
        load_frag(f1, st, aoff, boff, 32);   // overlap: issue ks=1 loads before ks=0 MMAs
        do_mma(acc, f0);
        do_mma(acc, f1);
        __syncthreads();   // protect stage reuse by next prefetch
    }

    // epilogue: float2 stores
#pragma unroll
    for (int ni = 0; ni < 4; ni++) {
        int col = bn + wn * 32 + ni * 8 + (lane & 3) * 2;
        float b0 = 0.f, b1 = 0.f;
        if (bias) { b0 = bias[col]; b1 = bias[col + 1]; }
#pragma unroll
        for (int mi = 0; mi < 2; mi++) {
            int row = bm + wm * 32 + mi * 16 + (lane >> 2);
            float2 v0 = make_float2(acc[mi][ni][0] + b0, acc[mi][ni][1] + b1);
            float2 v1 = make_float2(acc[mi][ni][2] + b0, acc[mi][ni][3] + b1);
            *(float2*)(C + (size_t)row * N + col) = v0;
            *(float2*)(C + (size_t)(row + 8) * N + col) = v1;
        }
    }
}

// ---------------- leaves ----------------
__global__ void leaf_act(const float* __restrict__ P, float* __restrict__ c_all,
                         float* __restrict__ h_all) {
    int idx = blockIdx.x * blockDim.x + threadIdx.x;  // 512*256*256
    int m = idx & 255;
    int rb = idx >> 8;
    long long row = 73LL * 256 + rb;
    const float* p = P + row * 1024;
    float i = sigf(p[m]);
    float o = sigf(p[256 + m]);
    float u = tanhf(p[512 + m]);
    float c = i * u;
    float h = o * tanhf(c);
    c_all[row * 256 + m] = c;
    h_all[row * 256 + m] = h;
}

// ---------------- weighted child h (split) + child-h sum (split) ----------------
__global__ void prep_level(const float* __restrict__ h_all, const float* __restrict__ prob,
                           __nv_bfloat16* __restrict__ hwh, __nv_bfloat16* __restrict__ hwl,
                           __nv_bfloat16* __restrict__ hsh, __nv_bfloat16* __restrict__ hsl,
                           int s) {
    int idx = blockIdx.x * blockDim.x + threadIdx.x;  // L*256*256
    int m = idx & 255;
    int b = (idx >> 8) & 255;
    int nl = idx >> 16;
    int n = s + nl;
    int c0 = n * 8 + 1;
    float sum = 0.f;
#pragma unroll
    for (int j = 0; j < 8; j++) {
        float w = prob[n * 585 + c0 + j];
        float hv = h_all[((long long)(c0 + j) * 256 + b) * 256 + m];
        float v = w * hv;
        long long off = ((long long)((nl * 8 + j) * 256 + b)) * 256 + m;
        split2(v, hwh[off], hwl[off]);
        sum += v;
    }
    split2(sum, hsh[idx], hsl[idx]);
}

// ---------------- combine ----------------
__global__ void combine_level(const float* __restrict__ P, const float* __restrict__ S,
                              const float* __restrict__ F, const float* __restrict__ prob,
                              float* __restrict__ c_all, float* __restrict__ h_all, int s) {
    int idx = blockIdx.x * blockDim.x + threadIdx.x;  // L*256*256
    int m = idx & 255;
    int b = (idx >> 8) & 255;
    int nl = idx >> 16;
    int n = s + nl;
    long long prow = (long long)n * 256 + b;
    const float* p = P + prow * 1024;
    const float* sp = S + (long long)(idx >> 8) * 768;
    float i = sigf(p[m] + sp[m]);
    float o = sigf(p[256 + m] + sp[256 + m]);
    float u = tanhf(p[512 + m] + sp[512 + m]);
    float fx = p[768 + m];
    float c = i * u;
    int c0 = n * 8 + 1;
#pragma unroll
    for (int j = 0; j < 8; j++) {
        float fpre = F[((long long)((nl * 8 + j) * 256 + b)) * 256 + m];  // has bfh
        float f = sigf(fpre + fx);
        float w = prob[n * 585 + c0 + j];
        float cc = c_all[((long long)(c0 + j) * 256 + b) * 256 + m];
        c += f * (w * cc);
    }
    float h = o * tanhf(c);
    c_all[prow * 256 + m] = c;
    h_all[prow * 256 + m] = h;
}

// ---------------- launch ----------------
extern "C" void kernel_launch(void* const* d_in, const int* in_sizes, int n_in,
                              void* d_out, int out_size) {
    const float* inputs = (const float*)d_in[0];
    const float* prob = (const float*)d_in[1];
    const float* Wioux = (const float*)d_in[2];
    const float* bioux = (const float*)d_in[3];
    const float* Wiouh = (const float*)d_in[4];
    const float* biouh = (const float*)d_in[5];
    const float* Wfx = (const float*)d_in[6];
    const float* bfx = (const float*)d_in[7];
    const float* Wfh = (const float*)d_in[8];
    const float* bfh = (const float*)d_in[9];
    float* h_all = (float*)d_out;

    float *P, *Call, *Sb, *Fb, *bc;
    __nv_bfloat16 *Ahi, *Alo, *Wchi, *Wclo, *Whhi, *Whlo, *Wfhi, *Wflo;
    __nv_bfloat16 *HShi, *HSlo, *HWhi, *HWlo;
    cudaGetSymbolAddress((void**)&P, g_P);
    cudaGetSymbolAddress((void**)&Call, g_c);
    cudaGetSymbolAddress((void**)&Sb, g_S);
    cudaGetSymbolAddress((void**)&Fb, g_F);
    cudaGetSymbolAddress((void**)&bc, g_bc);
    cudaGetSymbolAddress((void**)&Ahi, g_Ahi);
    cudaGetSymbolAddress((void**)&Alo, g_Alo);
    cudaGetSymbolAddress((void**)&Wchi, g_Wchi);
    cudaGetSymbolAddress((void**)&Wclo, g_Wclo);
    cudaGetSymbolAddress((void**)&Whhi, g_Whhi);
    cudaGetSymbolAddress((void**)&Whlo, g_Whlo);
    cudaGetSymbolAddress((void**)&Wfhi, g_Wfhi);
    cudaGetSymbolAddress((void**)&Wflo, g_Wflo);
    cudaGetSymbolAddress((void**)&HShi, g_HShi);
    cudaGetSymbolAddress((void**)&HSlo, g_HSlo);
    cudaGetSymbolAddress((void**)&HWhi, g_HWhi);
    cudaGetSymbolAddress((void**)&HWlo, g_HWlo);

    cudaFuncSetAttribute(tgemm, cudaFuncAttributeMaxDynamicSharedMemorySize, GEMM_SMEM);

    // conversions / packing
    conv_split<<<(int)((size_t)ROWS * 512 / 4 / 256), 256>>>(inputs, Ahi, Alo,
                                                             (long long)ROWS * 512 / 4);
    pack_wc<<<2048, 256>>>(Wioux, bioux, biouh, Wfx, bfx);
    conv_split<<<192, 256>>>(Wiouh, Whhi, Whlo, 768 * 256 / 4);
    conv_split<<<64, 256>>>(Wfh, Wfhi, Wflo, 256 * 256 / 4);

    // big input projection: P = X @ [Wioux;Wfx]^T + bias   (149760 x 1024 x 512)
    tgemm<<<dim3(8, ROWS / 128), 512, GEMM_SMEM>>>(Ahi, Alo, Wchi, Wclo, bc, P, ROWS, 1024, 512);

    // leaves
    leaf_act<<<(512 * 256 * 256) / 256, 256>>>(P, Call, h_all);

    // internal levels bottom-up
    const int starts[3] = {9, 1, 0};
    const int sizes[3] = {64, 8, 1};
    for (int l = 0; l < 3; l++) {
        int s = starts[l], L = sizes[l];
        prep_level<<<(L * 256 * 256) / 256, 256>>>(h_all, prob, HWhi, HWlo, HShi, HSlo, s);
        // S = hsum @ Wiouh^T   (L*256 x 768 x 256)
        tgemm<<<dim3(6, (L * 256) / 128), 512, GEMM_SMEM>>>(HShi, HSlo, Whhi, Whlo, nullptr, Sb,
                                                            L * 256, 768, 256);
        // F = hw @ Wfh^T + bfh (L*8*256 x 256 x 256)
        tgemm<<<dim3(2, (L * 8 * 256) / 128), 512, GEMM_SMEM>>>(HWhi, HWlo, Wfhi, Wflo, bfh, Fb,
                                                                L * 8 * 256, 256, 256);
        combine_level<<<(L * 256 * 256) / 256, 256>>>(P, Sb, Fb, prob, Call, h_all, s);
    }
}

// round 5
// speedup vs baseline: 3.3412x; 1.7697x over previous
#include <cuda_runtime.h>
#include <cuda_fp16.h>
#include <math.h>
#include <stdint.h>

#define NN 585
#define BATCH 256
#define MEM 256
#define ROWS (NN * BATCH)  // 149760

// ---------------- scratch (static device globals; no allocation) ----------------
__device__ __align__(128) float g_P[(size_t)ROWS * 1024];        // packed projections
__device__ __align__(128) float g_c[(size_t)NN * BATCH * MEM];   // c_all
__device__ __align__(128) float g_S[(size_t)64 * BATCH * 768];   // hsum @ Wiouh^T
__device__ __align__(128) float g_F[(size_t)512 * BATCH * MEM];  // hw @ Wfh^T + bfh
__device__ __align__(128) float g_bc[1024];                      // packed bias

// fp16 operands
__device__ __align__(128) __half g_Ah[(size_t)ROWS * 512];
__device__ __align__(128) __half g_Wc[1024 * 512];
__device__ __align__(128) __half g_Whh[768 * 256];
__device__ __align__(128) __half g_Wfh[256 * 256];
__device__ __align__(128) __half g_HS[64 * BATCH * 256];
__device__ __align__(128) __half g_HW[(size_t)512 * BATCH * 256];

// ---------------- helpers ----------------
__device__ __forceinline__ uint32_t smem_u32(const void* p) {
    uint32_t a;
    asm("{ .reg .u64 t; cvta.to.shared.u64 t, %1; cvt.u32.u64 %0, t; }" : "=r"(a) : "l"(p));
    return a;
}
__device__ __forceinline__ void cpa16(uint32_t dst, const void* src) {
    asm volatile("cp.async.cg.shared.global [%0], [%1], 16;" :: "r"(dst), "l"(src));
}
#define CP_COMMIT() asm volatile("cp.async.commit_group;" ::: "memory")

#define LDSM4(r, addr)                                                                  \
    asm volatile("ldmatrix.sync.aligned.m8n8.x4.shared.b16 {%0,%1,%2,%3}, [%4];"        \
                 : "=r"((r)[0]), "=r"((r)[1]), "=r"((r)[2]), "=r"((r)[3]) : "r"(addr))

#define MMAH(c, a, b0, b1)                                                              \
    asm volatile("mma.sync.aligned.m16n8k16.row.col.f32.f16.f16.f32 "                   \
                 "{%0,%1,%2,%3},{%4,%5,%6,%7},{%8,%9},{%0,%1,%2,%3};"                   \
                 : "+f"((c)[0]), "+f"((c)[1]), "+f"((c)[2]), "+f"((c)[3])               \
                 : "r"((a)[0]), "r"((a)[1]), "r"((a)[2]), "r"((a)[3]), "r"(b0), "r"(b1))

__device__ __forceinline__ float sigf(float x) { return 1.f / (1.f + expf(-x)); }

// ---------------- fp32 -> fp16 convert (vectorized) ----------------
__global__ void conv_half(const float* __restrict__ x, __half* __restrict__ y, long long n4) {
    long long i = blockIdx.x * (long long)blockDim.x + threadIdx.x;
    if (i >= n4) return;
    float4 v = ((const float4*)x)[i];
    ((__half2*)y)[i * 2 + 0] = __floats2half2_rn(v.x, v.y);
    ((__half2*)y)[i * 2 + 1] = __floats2half2_rn(v.z, v.w);
}

// ---------------- pack combined weight + bias ----------------
__global__ void pack_wc(const float* __restrict__ Wioux, const float* __restrict__ bioux,
                        const float* __restrict__ biouh, const float* __restrict__ Wfx,
                        const float* __restrict__ bfx) {
    int idx = blockIdx.x * blockDim.x + threadIdx.x;  // 1024*512
    int r = idx >> 9;
    int col = idx & 511;
    float w = (r < 768) ? Wioux[r * 512 + col] : Wfx[(r - 768) * 512 + col];
    g_Wc[idx] = __float2half(w);
    if (col == 0)
        g_bc[r] = (r < 768) ? (bioux[r] + biouh[r]) : bfx[r - 768];
}

// ============ mma.sync fp16 GEMM: C[M,N] = A[M,K]@B[N,K]^T (+bias[N]) ============
// 128x128x32 CTA tile, 512 threads (16 warps, 4x4), 4-stage cp.async pipeline.
// smem tiles padded to 80B row stride for conflict-free ldmatrix.
#define TILE_B   10240          // 128 rows * 80B
#define STAGE_B  (2 * TILE_B)   // A, B
#define NSTAGE   4
#define GEMM_SMEM (NSTAGE * STAGE_B)

__device__ __forceinline__ void load_stage(uint32_t dst, const __half* A0, const __half* B0,
                                           int K, int k0, int tid) {
    const __half* srcs[2] = {A0, B0};
#pragma unroll
    for (int i = 0; i < 2; i++) {
        int chunk = tid + i * 512;       // 0..1023
        int tile = chunk >> 9;
        int w = chunk & 511;
        int row = w >> 2, c = w & 3;
        cpa16(dst + tile * TILE_B + row * 80 + c * 16, srcs[tile] + (size_t)row * K + k0 + c * 8);
    }
    CP_COMMIT();
}

__global__ __launch_bounds__(512, 1)
void tgemm(const __half* __restrict__ A, const __half* __restrict__ B,
           const float* __restrict__ bias, float* __restrict__ C, int M, int N, int K) {
    extern __shared__ __align__(128) char smem[];
    uint32_t sb = smem_u32(smem);
    const int tid = threadIdx.x;
    const int warp = tid >> 5;
    const int lane = tid & 31;
    const int wm = warp >> 2;       // 0..3
    const int wn = warp & 3;        // 0..3
    const int bn = blockIdx.x * 128;
    const int bm = blockIdx.y * 128;
    const int NK = K >> 5;

    const __half* A0 = A + (size_t)bm * K;
    const __half* B0 = B + (size_t)bn * K;

    // prologue: fill pipeline (NSTAGE-1 stages in flight)
#pragma unroll
    for (int s = 0; s < NSTAGE - 1; s++)
        if (s < NK) load_stage(sb + s * STAGE_B, A0, B0, K, s * 32, tid);

    float acc[2][4][4];
#pragma unroll
    for (int mi = 0; mi < 2; mi++)
#pragma unroll
        for (int ni = 0; ni < 4; ni++)
#pragma unroll
            for (int r = 0; r < 4; r++) acc[mi][ni][r] = 0.f;

    // per-thread ldmatrix base offsets (tile-relative), 32x32 warp tile
    uint32_t aoff[2], boff[2];
#pragma unroll
    for (int mi = 0; mi < 2; mi++)
        aoff[mi] = (uint32_t)((wm * 32 + mi * 16 + (lane & 15)) * 80 + (lane >> 4) * 16);
#pragma unroll
    for (int np = 0; np < 2; np++)
        boff[np] = (uint32_t)((wn * 32 + np * 16 + (lane & 15)) * 80 + (lane >> 4) * 16);

    for (int k = 0; k < NK; k++) {
        int kpre = k + NSTAGE - 1;
        if (kpre < NK)
            load_stage(sb + (kpre % NSTAGE) * STAGE_B, A0, B0, K, kpre * 32, tid);
        int inflight = ((kpre < NK ? kpre : NK - 1)) - k;
        if (inflight >= 3)      asm volatile("cp.async.wait_group 3;" ::: "memory");
        else if (inflight == 2) asm volatile("cp.async.wait_group 2;" ::: "memory");
        else if (inflight == 1) asm volatile("cp.async.wait_group 1;" ::: "memory");
        else                    asm volatile("cp.async.wait_group 0;" ::: "memory");
        __syncthreads();

        uint32_t st = sb + (k % NSTAGE) * STAGE_B;
#pragma unroll
        for (int ks = 0; ks < 2; ks++) {
            uint32_t ko = ks * 32;
            uint32_t ah[2][4], bh[2][4];
#pragma unroll
            for (int mi = 0; mi < 2; mi++) LDSM4(ah[mi], st + aoff[mi] + ko);
#pragma unroll
            for (int np = 0; np < 2; np++) LDSM4(bh[np], st + TILE_B + boff[np] + ko);
#pragma unroll
            for (int mi = 0; mi < 2; mi++)
#pragma unroll
                for (int ni = 0; ni < 4; ni++) {
                    int np = ni >> 1, sub = ni & 1;
                    MMAH(acc[mi][ni], ah[mi], bh[np][sub], bh[np][sub + 2]);
                }
        }
        __syncthreads();   // protect stage reuse by next prefetch
    }

    // epilogue: float2 stores
#pragma unroll
    for (int ni = 0; ni < 4; ni++) {
        int col = bn + wn * 32 + ni * 8 + (lane & 3) * 2;
        float b0 = 0.f, b1 = 0.f;
        if (bias) { b0 = bias[col]; b1 = bias[col + 1]; }
#pragma unroll
        for (int mi = 0; mi < 2; mi++) {
            int row = bm + wm * 32 + mi * 16 + (lane >> 2);
            float2 v0 = make_float2(acc[mi][ni][0] + b0, acc[mi][ni][1] + b1);
            float2 v1 = make_float2(acc[mi][ni][2] + b0, acc[mi][ni][3] + b1);
            *(float2*)(C + (size_t)row * N + col) = v0;
            *(float2*)(C + (size_t)(row + 8) * N + col) = v1;
        }
    }
}

// ---------------- leaves ----------------
__global__ void leaf_act(const float* __restrict__ P, float* __restrict__ c_all,
                         float* __restrict__ h_all) {
    int idx = blockIdx.x * blockDim.x + threadIdx.x;  // 512*256*256
    int m = idx & 255;
    int rb = idx >> 8;
    long long row = 73LL * 256 + rb;
    const float* p = P + row * 1024;
    float i = sigf(p[m]);
    float o = sigf(p[256 + m]);
    float u = tanhf(p[512 + m]);
    float c = i * u;
    float h = o * tanhf(c);
    c_all[row * 256 + m] = c;
    h_all[row * 256 + m] = h;
}

// ---------------- weighted child h (fp16) + child-h sum (fp16) ----------------
__global__ void prep_level(const float* __restrict__ h_all, const float* __restrict__ prob,
                           __half* __restrict__ hw, __half* __restrict__ hs, int s) {
    int idx = blockIdx.x * blockDim.x + threadIdx.x;  // L*256*256
    int m = idx & 255;
    int b = (idx >> 8) & 255;
    int nl = idx >> 16;
    int n = s + nl;
    int c0 = n * 8 + 1;
    float sum = 0.f;
#pragma unroll
    for (int j = 0; j < 8; j++) {
        float w = prob[n * 585 + c0 + j];
        float hv = h_all[((long long)(c0 + j) * 256 + b) * 256 + m];
        float v = w * hv;
        hw[((long long)((nl * 8 + j) * 256 + b)) * 256 + m] = __float2half(v);
        sum += v;
    }
    hs[idx] = __float2half(sum);
}

// ---------------- combine ----------------
__global__ void combine_level(const float* __restrict__ P, const float* __restrict__ S,
                              const float* __restrict__ F, const float* __restrict__ prob,
                              float* __restrict__ c_all, float* __restrict__ h_all, int s) {
    int idx = blockIdx.x * blockDim.x + threadIdx.x;  // L*256*256
    int m = idx & 255;
    int b = (idx >> 8) & 255;
    int nl = idx >> 16;
    int n = s + nl;
    long long prow = (long long)n * 256 + b;
    const float* p = P + prow * 1024;
    const float* sp = S + (long long)(idx >> 8) * 768;
    float i = sigf(p[m] + sp[m]);
    float o = sigf(p[256 + m] + sp[256 + m]);
    float u = tanhf(p[512 + m] + sp[512 + m]);
    float fx = p[768 + m];
    float c = i * u;
    int c0 = n * 8 + 1;
#pragma unroll
    for (int j = 0; j < 8; j++) {
        float fpre = F[((long long)((nl * 8 + j) * 256 + b)) * 256 + m];  // has bfh
        float f = sigf(fpre + fx);
        float w = prob[n * 585 + c0 + j];
        float cc = c_all[((long long)(c0 + j) * 256 + b) * 256 + m];
        c += f * (w * cc);
    }
    float h = o * tanhf(c);
    c_all[prow * 256 + m] = c;
    h_all[prow * 256 + m] = h;
}

// ---------------- launch ----------------
extern "C" void kernel_launch(void* const* d_in, const int* in_sizes, int n_in,
                              void* d_out, int out_size) {
    const float* inputs = (const float*)d_in[0];
    const float* prob = (const float*)d_in[1];
    const float* Wioux = (const float*)d_in[2];
    const float* bioux = (const float*)d_in[3];
    const float* Wiouh = (const float*)d_in[4];
    const float* biouh = (const float*)d_in[5];
    const float* Wfx = (const float*)d_in[6];
    const float* bfx = (const float*)d_in[7];
    const float* Wfh = (const float*)d_in[8];
    const float* bfh = (const float*)d_in[9];
    float* h_all = (float*)d_out;

    float *P, *Call, *Sb, *Fb, *bc;
    __half *Ah, *Wc, *Whh, *Wf, *HS, *HW;
    cudaGetSymbolAddress((void**)&P, g_P);
    cudaGetSymbolAddress((void**)&Call, g_c);
    cudaGetSymbolAddress((void**)&Sb, g_S);
    cudaGetSymbolAddress((void**)&Fb, g_F);
    cudaGetSymbolAddress((void**)&bc, g_bc);
    cudaGetSymbolAddress((void**)&Ah, g_Ah);
    cudaGetSymbolAddress((void**)&Wc, g_Wc);
    cudaGetSymbolAddress((void**)&Whh, g_Whh);
    cudaGetSymbolAddress((void**)&Wf, g_Wfh);
    cudaGetSymbolAddress((void**)&HS, g_HS);
    cudaGetSymbolAddress((void**)&HW, g_HW);

    cudaFuncSetAttribute(tgemm, cudaFuncAttributeMaxDynamicSharedMemorySize, GEMM_SMEM);

    // conversions / packing
    conv_half<<<(int)((size_t)ROWS * 512 / 4 / 256), 256>>>(inputs, Ah, (long long)ROWS * 512 / 4);
    pack_wc<<<2048, 256>>>(Wioux, bioux, biouh, Wfx, bfx);
    conv_half<<<192, 256>>>(Wiouh, Whh, 768 * 256 / 4);
    conv_half<<<64, 256>>>(Wfh, Wf, 256 * 256 / 4);

    // big input projection: P = X @ [Wioux;Wfx]^T + bias   (149760 x 1024 x 512)
    tgemm<<<dim3(8, ROWS / 128), 512, GEMM_SMEM>>>(Ah, Wc, bc, P, ROWS, 1024, 512);

    // leaves
    leaf_act<<<(512 * 256 * 256) / 256, 256>>>(P, Call, h_all);

    // internal levels bottom-up
    const int starts[3] = {9, 1, 0};
    const int sizes[3] = {64, 8, 1};
    for (int l = 0; l < 3; l++) {
        int s = starts[l], L = sizes[l];
        prep_level<<<(L * 256 * 256) / 256, 256>>>(h_all, prob, HW, HS, s);
        // S = hsum @ Wiouh^T   (L*256 x 768 x 256)
        tgemm<<<dim3(6, (L * 256) / 128), 512, GEMM_SMEM>>>(HS, Whh, nullptr, Sb,
                                                            L * 256, 768, 256);
        // F = hw @ Wfh^T + bfh (L*8*256 x 256 x 256)
        tgemm<<<dim3(2, (L * 8 * 256) / 128), 512, GEMM_SMEM>>>(HW, Wf, bfh, Fb,
                                                                L * 8 * 256, 256, 256);
        combine_level<<<(L * 256 * 256) / 256, 256>>>(P, Sb, Fb, prob, Call, h_all, s);
    }
}

// round 6
// speedup vs baseline: 3.6997x; 1.1073x over previous
#include <cuda_runtime.h>
#include <cuda_fp16.h>
#include <math.h>
#include <stdint.h>

#define NN 585
#define BATCH 256
#define MEM 256
#define ROWS (NN * BATCH)       // 149760
#define IROWS (73 * 256)        // 18688 internal rows

// ---------------- scratch (static device globals; no allocation) ----------------
__device__ __align__(128) float g_Piou[(size_t)ROWS * 768];      // x@Wioux^T + biou
__device__ __align__(128) float g_Pfx[(size_t)IROWS * 256];      // x@Wfx^T + bfx (internal only)
__device__ __align__(128) float g_c[(size_t)NN * BATCH * MEM];   // c_all
__device__ __align__(128) float g_S[(size_t)64 * BATCH * 768];   // hsum @ Wiouh^T
__device__ __align__(128) float g_G[(size_t)512 * BATCH * MEM];  // h_children @ Wfh^T
__device__ __align__(128) float g_biou[768];

// fp16 operands
__device__ __align__(128) __half g_Ah[(size_t)ROWS * 512];
__device__ __align__(128) __half g_Wiou[768 * 512];
__device__ __align__(128) __half g_Wfx16[256 * 512];
__device__ __align__(128) __half g_Whh[768 * 256];
__device__ __align__(128) __half g_Wf16[256 * 256];
__device__ __align__(128) __half g_HS[64 * BATCH * 256];
__device__ __align__(128) __half g_h16[(size_t)NN * BATCH * MEM];

// ---------------- helpers ----------------
__device__ __forceinline__ uint32_t smem_u32(const void* p) {
    uint32_t a;
    asm("{ .reg .u64 t; cvta.to.shared.u64 t, %1; cvt.u32.u64 %0, t; }" : "=r"(a) : "l"(p));
    return a;
}
__device__ __forceinline__ void cpa16(uint32_t dst, const void* src) {
    asm volatile("cp.async.cg.shared.global [%0], [%1], 16;" :: "r"(dst), "l"(src));
}
#define CP_COMMIT() asm volatile("cp.async.commit_group;" ::: "memory")

#define LDSM4(r, addr)                                                                  \
    asm volatile("ldmatrix.sync.aligned.m8n8.x4.shared.b16 {%0,%1,%2,%3}, [%4];"        \
                 : "=r"((r)[0]), "=r"((r)[1]), "=r"((r)[2]), "=r"((r)[3]) : "r"(addr))

#define MMAH(c, a, b0, b1)                                                              \
    asm volatile("mma.sync.aligned.m16n8k16.row.col.f32.f16.f16.f32 "                   \
                 "{%0,%1,%2,%3},{%4,%5,%6,%7},{%8,%9},{%0,%1,%2,%3};"                   \
                 : "+f"((c)[0]), "+f"((c)[1]), "+f"((c)[2]), "+f"((c)[3])               \
                 : "r"((a)[0]), "r"((a)[1]), "r"((a)[2]), "r"((a)[3]), "r"(b0), "r"(b1))

__device__ __forceinline__ float sigf(float x) { return 1.f / (1.f + expf(-x)); }

// ---------------- fp32 -> fp16 convert (vectorized) ----------------
__global__ void conv_half(const float* __restrict__ x, __half* __restrict__ y, long long n4) {
    long long i = blockIdx.x * (long long)blockDim.x + threadIdx.x;
    if (i >= n4) return;
    float4 v = ((const float4*)x)[i];
    ((__half2*)y)[i * 2 + 0] = __floats2half2_rn(v.x, v.y);
    ((__half2*)y)[i * 2 + 1] = __floats2half2_rn(v.z, v.w);
}

// ---------------- pack iou weight + bias ----------------
__global__ void pack_wiou(const float* __restrict__ Wioux, const float* __restrict__ bioux,
                          const float* __restrict__ biouh) {
    int idx = blockIdx.x * blockDim.x + threadIdx.x;  // 768*512
    g_Wiou[idx] = __float2half(Wioux[idx]);
    if ((idx & 511) == 0) {
        int r = idx >> 9;
        g_biou[r] = bioux[r] + biouh[r];
    }
}

// ============ mma.sync fp16 GEMM: C[M,N] = A[M,K]@B[N,K]^T (+bias[N]) ============
// 128x128x32 CTA tile, 512 threads (16 warps, 4x4), 4-stage cp.async pipeline.
#define TILE_B   10240          // 128 rows * 80B
#define STAGE_B  (2 * TILE_B)   // A, B
#define NSTAGE   4
#define GEMM_SMEM (NSTAGE * STAGE_B)

__device__ __forceinline__ void load_stage(uint32_t dst, const __half* A0, const __half* B0,
                                           int K, int k0, int tid) {
    const __half* srcs[2] = {A0, B0};
#pragma unroll
    for (int i = 0; i < 2; i++) {
        int chunk = tid + i * 512;       // 0..1023
        int tile = chunk >> 9;
        int w = chunk & 511;
        int row = w >> 2, c = w & 3;
        cpa16(dst + tile * TILE_B + row * 80 + c * 16, srcs[tile] + (size_t)row * K + k0 + c * 8);
    }
    CP_COMMIT();
}

__global__ __launch_bounds__(512, 1)
void tgemm(const __half* __restrict__ A, const __half* __restrict__ B,
           const float* __restrict__ bias, float* __restrict__ C, int M, int N, int K) {
    extern __shared__ __align__(128) char smem[];
    uint32_t sb = smem_u32(smem);
    const int tid = threadIdx.x;
    const int warp = tid >> 5;
    const int lane = tid & 31;
    const int wm = warp >> 2;       // 0..3
    const int wn = warp & 3;        // 0..3
    const int bn = blockIdx.x * 128;
    const int bm = blockIdx.y * 128;
    const int NK = K >> 5;

    const __half* A0 = A + (size_t)bm * K;
    const __half* B0 = B + (size_t)bn * K;

#pragma unroll
    for (int s = 0; s < NSTAGE - 1; s++)
        if (s < NK) load_stage(sb + s * STAGE_B, A0, B0, K, s * 32, tid);

    float acc[2][4][4];
#pragma unroll
    for (int mi = 0; mi < 2; mi++)
#pragma unroll
        for (int ni = 0; ni < 4; ni++)
#pragma unroll
            for (int r = 0; r < 4; r++) acc[mi][ni][r] = 0.f;

    uint32_t aoff[2], boff[2];
#pragma unroll
    for (int mi = 0; mi < 2; mi++)
        aoff[mi] = (uint32_t)((wm * 32 + mi * 16 + (lane & 15)) * 80 + (lane >> 4) * 16);
#pragma unroll
    for (int np = 0; np < 2; np++)
        boff[np] = (uint32_t)((wn * 32 + np * 16 + (lane & 15)) * 80 + (lane >> 4) * 16);

    for (int k = 0; k < NK; k++) {
        int kpre = k + NSTAGE - 1;
        if (kpre < NK)
            load_stage(sb + (kpre % NSTAGE) * STAGE_B, A0, B0, K, kpre * 32, tid);
        int inflight = ((kpre < NK ? kpre : NK - 1)) - k;
        if (inflight >= 3)      asm volatile("cp.async.wait_group 3;" ::: "memory");
        else if (inflight == 2) asm volatile("cp.async.wait_group 2;" ::: "memory");
        else if (inflight == 1) asm volatile("cp.async.wait_group 1;" ::: "memory");
        else                    asm volatile("cp.async.wait_group 0;" ::: "memory");
        __syncthreads();

        uint32_t st = sb + (k % NSTAGE) * STAGE_B;
#pragma unroll
        for (int ks = 0; ks < 2; ks++) {
            uint32_t ko = ks * 32;
            uint32_t ah[2][4], bh[2][4];
#pragma unroll
            for (int mi = 0; mi < 2; mi++) LDSM4(ah[mi], st + aoff[mi] + ko);
#pragma unroll
            for (int np = 0; np < 2; np++) LDSM4(bh[np], st + TILE_B + boff[np] + ko);
#pragma unroll
            for (int mi = 0; mi < 2; mi++)
#pragma unroll
                for (int ni = 0; ni < 4; ni++) {
                    int np = ni >> 1, sub = ni & 1;
                    MMAH(acc[mi][ni], ah[mi], bh[np][sub], bh[np][sub + 2]);
                }
        }
        __syncthreads();
    }

#pragma unroll
    for (int ni = 0; ni < 4; ni++) {
        int col = bn + wn * 32 + ni * 8 + (lane & 3) * 2;
        float b0 = 0.f, b1 = 0.f;
        if (bias) { b0 = bias[col]; b1 = bias[col + 1]; }
#pragma unroll
        for (int mi = 0; mi < 2; mi++) {
            int row = bm + wm * 32 + mi * 16 + (lane >> 2);
            float2 v0 = make_float2(acc[mi][ni][0] + b0, acc[mi][ni][1] + b1);
            float2 v1 = make_float2(acc[mi][ni][2] + b0, acc[mi][ni][3] + b1);
            *(float2*)(C + (size_t)row * N + col) = v0;
            *(float2*)(C + (size_t)(row + 8) * N + col) = v1;
        }
    }
}

// ---------------- leaves: activation from P_iou, write c, h, h16 ----------------
__global__ void leaf_act(const float* __restrict__ Piou, float* __restrict__ c_all,
                         float* __restrict__ h_all, __half* __restrict__ h16) {
    int idx = blockIdx.x * blockDim.x + threadIdx.x;  // 512*256*256
    int m = idx & 255;
    int rb = idx >> 8;
    long long row = 73LL * 256 + rb;
    const float* p = Piou + row * 768;
    float i = sigf(p[m]);
    float o = sigf(p[256 + m]);
    float u = tanhf(p[512 + m]);
    float c = i * u;
    float h = o * tanhf(c);
    c_all[row * 256 + m] = c;
    h_all[row * 256 + m] = h;
    h16[row * 256 + m] = __float2half(h);
}

// ---------------- weighted child-h sum (fp16 out) ----------------
__global__ void prep_level(const float* __restrict__ h_all, const float* __restrict__ prob,
                           __half* __restrict__ hs, int s) {
    int idx = blockIdx.x * blockDim.x + threadIdx.x;  // L*256*256
    int m = idx & 255;
    int b = (idx >> 8) & 255;
    int nl = idx >> 16;
    int n = s + nl;
    int c0 = n * 8 + 1;
    float sum = 0.f;
#pragma unroll
    for (int j = 0; j < 8; j++) {
        float w = prob[n * 585 + c0 + j];
        float hv = h_all[((long long)(c0 + j) * 256 + b) * 256 + m];
        sum += w * hv;
    }
    hs[idx] = __float2half(sum);
}

// ---------------- combine: gates + cell update ----------------
__global__ void combine_level(const float* __restrict__ Piou, const float* __restrict__ S,
                              const float* __restrict__ G, const float* __restrict__ Pfx,
                              const float* __restrict__ bfh, const float* __restrict__ prob,
                              float* __restrict__ c_all, float* __restrict__ h_all,
                              __half* __restrict__ h16, int s) {
    int idx = blockIdx.x * blockDim.x + threadIdx.x;  // L*256*256
    int m = idx & 255;
    int b = (idx >> 8) & 255;
    int nl = idx >> 16;
    int n = s + nl;
    long long prow = (long long)n * 256 + b;
    const float* p = Piou + prow * 768;
    const float* sp = S + (long long)(idx >> 8) * 768;
    float i = sigf(p[m] + sp[m]);
    float o = sigf(p[256 + m] + sp[256 + m]);
    float u = tanhf(p[512 + m] + sp[512 + m]);
    float fx = Pfx[prow * 256 + m] + bfh[m];
    float c = i * u;
    int c0 = n * 8 + 1;
    int gbase = (n - s) * 8;    // child row block within G (children contiguous from s*8+1)
#pragma unroll
    for (int j = 0; j < 8; j++) {
        float g = G[((long long)((gbase + j) * 256 + b)) * 256 + m];
        float w = prob[n * 585 + c0 + j];
        float f = sigf(w * g + fx);
        float cc = c_all[((long long)(c0 + j) * 256 + b) * 256 + m];
        c += f * (w * cc);
    }
    float h = o * tanhf(c);
    c_all[prow * 256 + m] = c;
    h_all[prow * 256 + m] = h;
    h16[prow * 256 + m] = __float2half(h);
}

// ---------------- launch ----------------
extern "C" void kernel_launch(void* const* d_in, const int* in_sizes, int n_in,
                              void* d_out, int out_size) {
    const float* inputs = (const float*)d_in[0];
    const float* prob = (const float*)d_in[1];
    const float* Wioux = (const float*)d_in[2];
    const float* bioux = (const float*)d_in[3];
    const float* Wiouh = (const float*)d_in[4];
    const float* biouh = (const float*)d_in[5];
    const float* Wfx = (const float*)d_in[6];
    const float* bfx = (const float*)d_in[7];
    const float* Wfh = (const float*)d_in[8];
    const float* bfh = (const float*)d_in[9];
    float* h_all = (float*)d_out;

    float *Piou, *Pfx, *Call, *Sb, *Gb, *biou;
    __half *Ah, *Wiou16, *Wfx16, *Whh, *Wf16, *HS, *h16;
    cudaGetSymbolAddress((void**)&Piou, g_Piou);
    cudaGetSymbolAddress((void**)&Pfx, g_Pfx);
    cudaGetSymbolAddress((void**)&Call, g_c);
    cudaGetSymbolAddress((void**)&Sb, g_S);
    cudaGetSymbolAddress((void**)&Gb, g_G);
    cudaGetSymbolAddress((void**)&biou, g_biou);
    cudaGetSymbolAddress((void**)&Ah, g_Ah);
    cudaGetSymbolAddress((void**)&Wiou16, g_Wiou);
    cudaGetSymbolAddress((void**)&Wfx16, g_Wfx16);
    cudaGetSymbolAddress((void**)&Whh, g_Whh);
    cudaGetSymbolAddress((void**)&Wf16, g_Wf16);
    cudaGetSymbolAddress((void**)&HS, g_HS);
    cudaGetSymbolAddress((void**)&h16, g_h16);

    cudaFuncSetAttribute(tgemm, cudaFuncAttributeMaxDynamicSharedMemorySize, GEMM_SMEM);

    // conversions / packing
    conv_half<<<(int)((size_t)ROWS * 512 / 4 / 256), 256>>>(inputs, Ah, (long long)ROWS * 512 / 4);
    pack_wiou<<<(768 * 512) / 256, 256>>>(Wioux, bioux, biouh);
    conv_half<<<128, 256>>>(Wfx, Wfx16, 256 * 512 / 4);
    conv_half<<<192, 256>>>(Wiouh, Whh, 768 * 256 / 4);
    conv_half<<<64, 256>>>(Wfh, Wf16, 256 * 256 / 4);

    // P_iou = X @ Wioux^T + (bioux+biouh)     (149760 x 768 x 512)
    tgemm<<<dim3(6, ROWS / 128), 512, GEMM_SMEM>>>(Ah, Wiou16, biou, Piou, ROWS, 768, 512);
    // P_fx = X[internal] @ Wfx^T + bfx        (18688 x 256 x 512)
    tgemm<<<dim3(2, IROWS / 128), 512, GEMM_SMEM>>>(Ah, Wfx16, bfx, Pfx, IROWS, 256, 512);

    // leaves
    leaf_act<<<(512 * 256 * 256) / 256, 256>>>(Piou, Call, h_all, h16);

    // internal levels bottom-up
    const int starts[3] = {9, 1, 0};
    const int sizes[3] = {64, 8, 1};
    for (int l = 0; l < 3; l++) {
        int s = starts[l], L = sizes[l];
        int childRows = L * 8 * 256;
        // G = h16[children] @ Wfh^T            (childRows x 256 x 256), bfh added in combine
        tgemm<<<dim3(2, childRows / 128), 512, GEMM_SMEM>>>(
            h16 + (size_t)(s * 8 + 1) * 256 * 256, Wf16, nullptr, Gb, childRows, 256, 256);
        // hsum
        prep_level<<<(L * 256 * 256) / 256, 256>>>(h_all, prob, HS, s);
        // S = hsum @ Wiouh^T                   (L*256 x 768 x 256)
        tgemm<<<dim3(6, (L * 256) / 128), 512, GEMM_SMEM>>>(HS, Whh, nullptr, Sb,
                                                            L * 256, 768, 256);
        combine_level<<<(L * 256 * 256) / 256, 256>>>(Piou, Sb, Gb, Pfx, bfh, prob,
                                                      Call, h_all, h16, s);
    }
}

// round 7
// speedup vs baseline: 3.7939x; 1.0255x over previous
#include <cuda_runtime.h>
#include <cuda_fp16.h>
#include <math.h>
#include <stdint.h>

#define NN 585
#define BATCH 256
#define MEM 256
#define ROWS (NN * BATCH)       // 149760
#define IROWS (73 * 256)        // 18688 internal rows

// ---------------- scratch (static device globals; no allocation) ----------------
__device__ __align__(128) __half g_Piou[(size_t)ROWS * 768];     // x@Wioux^T + biou (fp16)
__device__ __align__(128) __half g_Pfx[(size_t)IROWS * 256];     // x@Wfx^T + bfx (fp16)
__device__ __align__(128) float g_c[(size_t)NN * BATCH * MEM];   // c_all
__device__ __align__(128) float g_S[(size_t)64 * BATCH * 768];   // hsum @ Wiouh^T (fp32)
__device__ __align__(128) __half g_G[(size_t)512 * BATCH * MEM]; // h_children @ Wfh^T (fp16)
__device__ __align__(128) float g_biou[768];

// fp16 operands
__device__ __align__(128) __half g_Ah[(size_t)ROWS * 512];
__device__ __align__(128) __half g_Wiou[768 * 512];
__device__ __align__(128) __half g_Wfx16[256 * 512];
__device__ __align__(128) __half g_Whh[768 * 256];
__device__ __align__(128) __half g_Wf16[256 * 256];
__device__ __align__(128) __half g_HS[64 * BATCH * 256];
__device__ __align__(128) __half g_h16[(size_t)NN * BATCH * MEM];

// ---------------- helpers ----------------
__device__ __forceinline__ uint32_t smem_u32(const void* p) {
    uint32_t a;
    asm("{ .reg .u64 t; cvta.to.shared.u64 t, %1; cvt.u32.u64 %0, t; }" : "=r"(a) : "l"(p));
    return a;
}
__device__ __forceinline__ void cpa16(uint32_t dst, const void* src) {
    asm volatile("cp.async.cg.shared.global [%0], [%1], 16;" :: "r"(dst), "l"(src));
}
#define CP_COMMIT() asm volatile("cp.async.commit_group;" ::: "memory")

#define LDSM4(r, addr)                                                                  \
    asm volatile("ldmatrix.sync.aligned.m8n8.x4.shared.b16 {%0,%1,%2,%3}, [%4];"        \
                 : "=r"((r)[0]), "=r"((r)[1]), "=r"((r)[2]), "=r"((r)[3]) : "r"(addr))

#define MMAH(c, a, b0, b1)                                                              \
    asm volatile("mma.sync.aligned.m16n8k16.row.col.f32.f16.f16.f32 "                   \
                 "{%0,%1,%2,%3},{%4,%5,%6,%7},{%8,%9},{%0,%1,%2,%3};"                   \
                 : "+f"((c)[0]), "+f"((c)[1]), "+f"((c)[2]), "+f"((c)[3])               \
                 : "r"((a)[0]), "r"((a)[1]), "r"((a)[2]), "r"((a)[3]), "r"(b0), "r"(b1))

__device__ __forceinline__ float sigf(float x) { return 1.f / (1.f + expf(-x)); }

// ---------------- fp32 -> fp16 convert (vectorized) ----------------
__global__ void conv_half(const float* __restrict__ x, __half* __restrict__ y, long long n4) {
    long long i = blockIdx.x * (long long)blockDim.x + threadIdx.x;
    if (i >= n4) return;
    float4 v = ((const float4*)x)[i];
    ((__half2*)y)[i * 2 + 0] = __floats2half2_rn(v.x, v.y);
    ((__half2*)y)[i * 2 + 1] = __floats2half2_rn(v.z, v.w);
}

// ---------------- pack iou weight + bias ----------------
__global__ void pack_wiou(const float* __restrict__ Wioux, const float* __restrict__ bioux,
                          const float* __restrict__ biouh) {
    int idx = blockIdx.x * blockDim.x + threadIdx.x;  // 768*512
    g_Wiou[idx] = __float2half(Wioux[idx]);
    if ((idx & 511) == 0) {
        int r = idx >> 9;
        g_biou[r] = bioux[r] + biouh[r];
    }
}

// ============ mma.sync fp16 GEMM: C[M,N] = A[M,K]@B[N,K]^T (+bias[N]) ============
// 128x128x32 CTA tile, 512 threads (16 warps, 4x4), 4-stage cp.async pipeline.
// Output: fp32 (Cf) or fp16 (Ch) — exactly one of the two is non-null.
#define TILE_B   10240          // 128 rows * 80B
#define STAGE_B  (2 * TILE_B)   // A, B
#define NSTAGE   4
#define GEMM_SMEM (NSTAGE * STAGE_B)

__device__ __forceinline__ void load_stage(uint32_t dst, const __half* A0, const __half* B0,
                                           int K, int k0, int tid) {
    const __half* srcs[2] = {A0, B0};
#pragma unroll
    for (int i = 0; i < 2; i++) {
        int chunk = tid + i * 512;       // 0..1023
        int tile = chunk >> 9;
        int w = chunk & 511;
        int row = w >> 2, c = w & 3;
        cpa16(dst + tile * TILE_B + row * 80 + c * 16, srcs[tile] + (size_t)row * K + k0 + c * 8);
    }
    CP_COMMIT();
}

__global__ __launch_bounds__(512, 1)
void tgemm(const __half* __restrict__ A, const __half* __restrict__ B,
           const float* __restrict__ bias, float* __restrict__ Cf,
           __half* __restrict__ Ch, int M, int N, int K) {
    extern __shared__ __align__(128) char smem[];
    uint32_t sb = smem_u32(smem);
    const int tid = threadIdx.x;
    const int warp = tid >> 5;
    const int lane = tid & 31;
    const int wm = warp >> 2;       // 0..3
    const int wn = warp & 3;        // 0..3
    const int bn = blockIdx.x * 128;
    const int bm = blockIdx.y * 128;
    const int NK = K >> 5;

    const __half* A0 = A + (size_t)bm * K;
    const __half* B0 = B + (size_t)bn * K;

#pragma unroll
    for (int s = 0; s < NSTAGE - 1; s++)
        if (s < NK) load_stage(sb + s * STAGE_B, A0, B0, K, s * 32, tid);

    float acc[2][4][4];
#pragma unroll
    for (int mi = 0; mi < 2; mi++)
#pragma unroll
        for (int ni = 0; ni < 4; ni++)
#pragma unroll
            for (int r = 0; r < 4; r++) acc[mi][ni][r] = 0.f;

    uint32_t aoff[2], boff[2];
#pragma unroll
    for (int mi = 0; mi < 2; mi++)
        aoff[mi] = (uint32_t)((wm * 32 + mi * 16 + (lane & 15)) * 80 + (lane >> 4) * 16);
#pragma unroll
    for (int np = 0; np < 2; np++)
        boff[np] = (uint32_t)((wn * 32 + np * 16 + (lane & 15)) * 80 + (lane >> 4) * 16);

    for (int k = 0; k < NK; k++) {
        int kpre = k + NSTAGE - 1;
        if (kpre < NK)
            load_stage(sb + (kpre % NSTAGE) * STAGE_B, A0, B0, K, kpre * 32, tid);
        int inflight = ((kpre < NK ? kpre : NK - 1)) - k;
        if (inflight >= 3)      asm volatile("cp.async.wait_group 3;" ::: "memory");
        else if (inflight == 2) asm volatile("cp.async.wait_group 2;" ::: "memory");
        else if (inflight == 1) asm volatile("cp.async.wait_group 1;" ::: "memory");
        else                    asm volatile("cp.async.wait_group 0;" ::: "memory");
        __syncthreads();

        uint32_t st = sb + (k % NSTAGE) * STAGE_B;
#pragma unroll
        for (int ks = 0; ks < 2; ks++) {
            uint32_t ko = ks * 32;
            uint32_t ah[2][4], bh[2][4];
#pragma unroll
            for (int mi = 0; mi < 2; mi++) LDSM4(ah[mi], st + aoff[mi] + ko);
#pragma unroll
            for (int np = 0; np < 2; np++) LDSM4(bh[np], st + TILE_B + boff[np] + ko);
#pragma unroll
            for (int mi = 0; mi < 2; mi++)
#pragma unroll
                for (int ni = 0; ni < 4; ni++) {
                    int np = ni >> 1, sub = ni & 1;
                    MMAH(acc[mi][ni], ah[mi], bh[np][sub], bh[np][sub + 2]);
                }
        }
        __syncthreads();
    }

#pragma unroll
    for (int ni = 0; ni < 4; ni++) {
        int col = bn + wn * 32 + ni * 8 + (lane & 3) * 2;
        float b0 = 0.f, b1 = 0.f;
        if (bias) { b0 = bias[col]; b1 = bias[col + 1]; }
#pragma unroll
        for (int mi = 0; mi < 2; mi++) {
            int row = bm + wm * 32 + mi * 16 + (lane >> 2);
            float2 v0 = make_float2(acc[mi][ni][0] + b0, acc[mi][ni][1] + b1);
            float2 v1 = make_float2(acc[mi][ni][2] + b0, acc[mi][ni][3] + b1);
            if (Ch) {
                *(__half2*)(Ch + (size_t)row * N + col) = __floats2half2_rn(v0.x, v0.y);
                *(__half2*)(Ch + (size_t)(row + 8) * N + col) = __floats2half2_rn(v1.x, v1.y);
            } else {
                *(float2*)(Cf + (size_t)row * N + col) = v0;
                *(float2*)(Cf + (size_t)(row + 8) * N + col) = v1;
            }
        }
    }
}

// ---------------- leaves: activation from fp16 P_iou ----------------
__global__ void leaf_act(const __half* __restrict__ Piou, float* __restrict__ c_all,
                         float* __restrict__ h_all, __half* __restrict__ h16) {
    int idx = blockIdx.x * blockDim.x + threadIdx.x;  // 512*256*256
    int m = idx & 255;
    int rb = idx >> 8;
    long long row = 73LL * 256 + rb;
    const __half* p = Piou + row * 768;
    float i = sigf(__half2float(p[m]));
    float o = sigf(__half2float(p[256 + m]));
    float u = tanhf(__half2float(p[512 + m]));
    float c = i * u;
    float h = o * tanhf(c);
    c_all[row * 256 + m] = c;
    h_all[row * 256 + m] = h;
    h16[row * 256 + m] = __float2half(h);
}

// ---------------- weighted child-h sum (fp16 out) ----------------
__global__ void prep_level(const float* __restrict__ h_all, const float* __restrict__ prob,
                           __half* __restrict__ hs, int s) {
    int idx = blockIdx.x * blockDim.x + threadIdx.x;  // L*256*256
    int m = idx & 255;
    int b = (idx >> 8) & 255;
    int nl = idx >> 16;
    int n = s + nl;
    int c0 = n * 8 + 1;
    float sum = 0.f;
#pragma unroll
    for (int j = 0; j < 8; j++) {
        float w = prob[n * 585 + c0 + j];
        float hv = h_all[((long long)(c0 + j) * 256 + b) * 256 + m];
        sum += w * hv;
    }
    hs[idx] = __float2half(sum);
}

// ---------------- combine: gates + cell update ----------------
__global__ void combine_level(const __half* __restrict__ Piou, const float* __restrict__ S,
                              const __half* __restrict__ G, const __half* __restrict__ Pfx,
                              const float* __restrict__ bfh, const float* __restrict__ prob,
                              float* __restrict__ c_all, float* __restrict__ h_all,
                              __half* __restrict__ h16, int s) {
    int idx = blockIdx.x * blockDim.x + threadIdx.x;  // L*256*256
    int m = idx & 255;
    int b = (idx >> 8) & 255;
    int nl = idx >> 16;
    int n = s + nl;
    long long prow = (long long)n * 256 + b;
    const __half* p = Piou + prow * 768;
    const float* sp = S + (long long)(idx >> 8) * 768;
    float i = sigf(__half2float(p[m]) + sp[m]);
    float o = sigf(__half2float(p[256 + m]) + sp[256 + m]);
    float u = tanhf(__half2float(p[512 + m]) + sp[512 + m]);
    float fx = __half2float(Pfx[prow * 256 + m]) + bfh[m];
    float c = i * u;
    int c0 = n * 8 + 1;
    int gbase = (n - s) * 8;    // child row block within G
#pragma unroll
    for (int j = 0; j < 8; j++) {
        float g = __half2float(G[((long long)((gbase + j) * 256 + b)) * 256 + m]);
        float w = prob[n * 585 + c0 + j];
        float f = sigf(w * g + fx);
        float cc = c_all[((long long)(c0 + j) * 256 + b) * 256 + m];
        c += f * (w * cc);
    }
    float h = o * tanhf(c);
    c_all[prow * 256 + m] = c;
    h_all[prow * 256 + m] = h;
    h16[prow * 256 + m] = __float2half(h);
}

// ---------------- launch ----------------
extern "C" void kernel_launch(void* const* d_in, const int* in_sizes, int n_in,
                              void* d_out, int out_size) {
    const float* inputs = (const float*)d_in[0];
    const float* prob = (const float*)d_in[1];
    const float* Wioux = (const float*)d_in[2];
    const float* bioux = (const float*)d_in[3];
    const float* Wiouh = (const float*)d_in[4];
    const float* biouh = (const float*)d_in[5];
    const float* Wfx = (const float*)d_in[6];
    const float* bfx = (const float*)d_in[7];
    const float* Wfh = (const float*)d_in[8];
    const float* bfh = (const float*)d_in[9];
    float* h_all = (float*)d_out;

    float *Call, *Sb, *biou;
    __half *Piou, *Pfx, *Gb, *Ah, *Wiou16, *Wfx16, *Whh, *Wf16, *HS, *h16;
    cudaGetSymbolAddress((void**)&Piou, g_Piou);
    cudaGetSymbolAddress((void**)&Pfx, g_Pfx);
    cudaGetSymbolAddress((void**)&Call, g_c);
    cudaGetSymbolAddress((void**)&Sb, g_S);
    cudaGetSymbolAddress((void**)&Gb, g_G);
    cudaGetSymbolAddress((void**)&biou, g_biou);
    cudaGetSymbolAddress((void**)&Ah, g_Ah);
    cudaGetSymbolAddress((void**)&Wiou16, g_Wiou);
    cudaGetSymbolAddress((void**)&Wfx16, g_Wfx16);
    cudaGetSymbolAddress((void**)&Whh, g_Whh);
    cudaGetSymbolAddress((void**)&Wf16, g_Wf16);
    cudaGetSymbolAddress((void**)&HS, g_HS);
    cudaGetSymbolAddress((void**)&h16, g_h16);

    cudaFuncSetAttribute(tgemm, cudaFuncAttributeMaxDynamicSharedMemorySize, GEMM_SMEM);

    // conversions / packing
    conv_half<<<(int)((size_t)ROWS * 512 / 4 / 256), 256>>>(inputs, Ah, (long long)ROWS * 512 / 4);
    pack_wiou<<<(768 * 512) / 256, 256>>>(Wioux, bioux, biouh);
    conv_half<<<128, 256>>>(Wfx, Wfx16, 256 * 512 / 4);
    conv_half<<<192, 256>>>(Wiouh, Whh, 768 * 256 / 4);
    conv_half<<<64, 256>>>(Wfh, Wf16, 256 * 256 / 4);

    // P_iou = X @ Wioux^T + (bioux+biouh)     (149760 x 768 x 512) -> fp16
    tgemm<<<dim3(6, ROWS / 128), 512, GEMM_SMEM>>>(Ah, Wiou16, biou, nullptr, Piou,
                                                   ROWS, 768, 512);
    // P_fx = X[internal] @ Wfx^T + bfx        (18688 x 256 x 512) -> fp16
    tgemm<<<dim3(2, IROWS / 128), 512, GEMM_SMEM>>>(Ah, Wfx16, bfx, nullptr, Pfx,
                                                    IROWS, 256, 512);

    // leaves
    leaf_act<<<(512 * 256 * 256) / 256, 256>>>(Piou, Call, h_all, h16);

    // internal levels bottom-up
    const int starts[3] = {9, 1, 0};
    const int sizes[3] = {64, 8, 1};
    for (int l = 0; l < 3; l++) {
        int s = starts[l], L = sizes[l];
        int childRows = L * 8 * 256;
        // G = h16[children] @ Wfh^T            (childRows x 256 x 256) -> fp16
        tgemm<<<dim3(2, childRows / 128), 512, GEMM_SMEM>>>(
            h16 + (size_t)(s * 8 + 1) * 256 * 256, Wf16, nullptr, nullptr, Gb,
            childRows, 256, 256);
        // hsum
        prep_level<<<(L * 256 * 256) / 256, 256>>>(h_all, prob, HS, s);
        // S = hsum @ Wiouh^T                   (L*256 x 768 x 256) -> fp32
        tgemm<<<dim3(6, (L * 256) / 128), 512, GEMM_SMEM>>>(HS, Whh, nullptr, Sb, nullptr,
                                                            L * 256, 768, 256);
        combine_level<<<(L * 256 * 256) / 256, 256>>>(Piou, Sb, Gb, Pfx, bfh, prob,
                                                      Call, h_all, h16, s);
    }
}

// round 8
// speedup vs baseline: 5.0965x; 1.3433x over previous
#include <cuda_runtime.h>
#include <cuda_fp16.h>
#include <math.h>
#include <stdint.h>

#define NN 585
#define BATCH 256
#define MEM 256
#define ROWS (NN * BATCH)       // 149760
#define IROWS (73 * 256)        // 18688 internal rows
#define PLANE ((size_t)ROWS * 256)

// ---------------- scratch (static device globals; no allocation) ----------------
__device__ __align__(128) __half g_P[3 * PLANE];                 // gate-planar P_iou (internal rows used)
__device__ __align__(128) __half g_Pfx[(size_t)IROWS * 256];     // x@Wfx^T + bfx (fp16)
__device__ __align__(128) __half g_c16[(size_t)NN * BATCH * MEM];// c_all (fp16)
__device__ __align__(128) float g_S[(size_t)64 * BATCH * 768];   // hsum @ Wiouh^T (fp32)
__device__ __align__(128) __half g_G[(size_t)512 * BATCH * MEM]; // h_children @ Wfh^T (fp16)
__device__ __align__(128) float g_biou[768];

// fp16 operands
__device__ __align__(128) __half g_Ah[(size_t)ROWS * 512];
__device__ __align__(128) __half g_Wiou[768 * 512];
__device__ __align__(128) __half g_Wfx16[256 * 512];
__device__ __align__(128) __half g_Whh[768 * 256];
__device__ __align__(128) __half g_Wf16[256 * 256];
__device__ __align__(128) __half g_HS[64 * BATCH * 256];
__device__ __align__(128) __half g_h16[(size_t)NN * BATCH * MEM];

// ---------------- helpers ----------------
__device__ __forceinline__ uint32_t smem_u32(const void* p) {
    uint32_t a;
    asm("{ .reg .u64 t; cvta.to.shared.u64 t, %1; cvt.u32.u64 %0, t; }" : "=r"(a) : "l"(p));
    return a;
}
__device__ __forceinline__ void cpa16(uint32_t dst, const void* src) {
    asm volatile("cp.async.cg.shared.global [%0], [%1], 16;" :: "r"(dst), "l"(src));
}
#define CP_COMMIT() asm volatile("cp.async.commit_group;" ::: "memory")

#define LDSM4(r, addr)                                                                  \
    asm volatile("ldmatrix.sync.aligned.m8n8.x4.shared.b16 {%0,%1,%2,%3}, [%4];"        \
                 : "=r"((r)[0]), "=r"((r)[1]), "=r"((r)[2]), "=r"((r)[3]) : "r"(addr))

#define MMAH(c, a, b0, b1)                                                              \
    asm volatile("mma.sync.aligned.m16n8k16.row.col.f32.f16.f16.f32 "                   \
                 "{%0,%1,%2,%3},{%4,%5,%6,%7},{%8,%9},{%0,%1,%2,%3};"                   \
                 : "+f"((c)[0]), "+f"((c)[1]), "+f"((c)[2]), "+f"((c)[3])               \
                 : "r"((a)[0]), "r"((a)[1]), "r"((a)[2]), "r"((a)[3]), "r"(b0), "r"(b1))

__device__ __forceinline__ float sigf(float x) { return 1.f / (1.f + expf(-x)); }

// ---------------- fp32 -> fp16 convert (vectorized) ----------------
__global__ void conv_half(const float* __restrict__ x, __half* __restrict__ y, long long n4) {
    long long i = blockIdx.x * (long long)blockDim.x + threadIdx.x;
    if (i >= n4) return;
    float4 v = ((const float4*)x)[i];
    ((__half2*)y)[i * 2 + 0] = __floats2half2_rn(v.x, v.y);
    ((__half2*)y)[i * 2 + 1] = __floats2half2_rn(v.z, v.w);
}

// ---------------- pack iou weight + bias ----------------
__global__ void pack_wiou(const float* __restrict__ Wioux, const float* __restrict__ bioux,
                          const float* __restrict__ biouh) {
    int idx = blockIdx.x * blockDim.x + threadIdx.x;  // 768*512
    g_Wiou[idx] = __float2half(Wioux[idx]);
    if ((idx & 511) == 0) {
        int r = idx >> 9;
        g_biou[r] = bioux[r] + biouh[r];
    }
}

// ============ generic mma.sync fp16 GEMM (used for Pfx, G, S) ============
#define TILE_B   10240          // 128 rows * 80B
#define STAGE_B  (2 * TILE_B)
#define NSTAGE   4
#define GEMM_SMEM (NSTAGE * STAGE_B)

__device__ __forceinline__ void load_stage(uint32_t dst, const __half* A0, const __half* B0,
                                           int K, int k0, int tid) {
    const __half* srcs[2] = {A0, B0};
#pragma unroll
    for (int i = 0; i < 2; i++) {
        int chunk = tid + i * 512;
        int tile = chunk >> 9;
        int w = chunk & 511;
        int row = w >> 2, c = w & 3;
        cpa16(dst + tile * TILE_B + row * 80 + c * 16, srcs[tile] + (size_t)row * K + k0 + c * 8);
    }
    CP_COMMIT();
}

__global__ __launch_bounds__(512, 1)
void tgemm(const __half* __restrict__ A, const __half* __restrict__ B,
           const float* __restrict__ bias, float* __restrict__ Cf,
           __half* __restrict__ Ch, int M, int N, int K) {
    extern __shared__ __align__(128) char smem[];
    uint32_t sb = smem_u32(smem);
    const int tid = threadIdx.x;
    const int warp = tid >> 5;
    const int lane = tid & 31;
    const int wm = warp >> 2;
    const int wn = warp & 3;
    const int bn = blockIdx.x * 128;
    const int bm = blockIdx.y * 128;
    const int NK = K >> 5;

    const __half* A0 = A + (size_t)bm * K;
    const __half* B0 = B + (size_t)bn * K;

#pragma unroll
    for (int s = 0; s < NSTAGE - 1; s++)
        if (s < NK) load_stage(sb + s * STAGE_B, A0, B0, K, s * 32, tid);

    float acc[2][4][4];
#pragma unroll
    for (int mi = 0; mi < 2; mi++)
#pragma unroll
        for (int ni = 0; ni < 4; ni++)
#pragma unroll
            for (int r = 0; r < 4; r++) acc[mi][ni][r] = 0.f;

    uint32_t aoff[2], boff[2];
#pragma unroll
    for (int mi = 0; mi < 2; mi++)
        aoff[mi] = (uint32_t)((wm * 32 + mi * 16 + (lane & 15)) * 80 + (lane >> 4) * 16);
#pragma unroll
    for (int np = 0; np < 2; np++)
        boff[np] = (uint32_t)((wn * 32 + np * 16 + (lane & 15)) * 80 + (lane >> 4) * 16);

    for (int k = 0; k < NK; k++) {
        int kpre = k + NSTAGE - 1;
        if (kpre < NK)
            load_stage(sb + (kpre % NSTAGE) * STAGE_B, A0, B0, K, kpre * 32, tid);
        int inflight = ((kpre < NK ? kpre : NK - 1)) - k;
        if (inflight >= 3)      asm volatile("cp.async.wait_group 3;" ::: "memory");
        else if (inflight == 2) asm volatile("cp.async.wait_group 2;" ::: "memory");
        else if (inflight == 1) asm volatile("cp.async.wait_group 1;" ::: "memory");
        else                    asm volatile("cp.async.wait_group 0;" ::: "memory");
        __syncthreads();

        uint32_t st = sb + (k % NSTAGE) * STAGE_B;
#pragma unroll
        for (int ks = 0; ks < 2; ks++) {
            uint32_t ko = ks * 32;
            uint32_t ah[2][4], bh[2][4];
#pragma unroll
            for (int mi = 0; mi < 2; mi++) LDSM4(ah[mi], st + aoff[mi] + ko);
#pragma unroll
            for (int np = 0; np < 2; np++) LDSM4(bh[np], st + TILE_B + boff[np] + ko);
#pragma unroll
            for (int mi = 0; mi < 2; mi++)
#pragma unroll
                for (int ni = 0; ni < 4; ni++) {
                    int np = ni >> 1, sub = ni & 1;
                    MMAH(acc[mi][ni], ah[mi], bh[np][sub], bh[np][sub + 2]);
                }
        }
        __syncthreads();
    }

#pragma unroll
    for (int ni = 0; ni < 4; ni++) {
        int col = bn + wn * 32 + ni * 8 + (lane & 3) * 2;
        float b0 = 0.f, b1 = 0.f;
        if (bias) { b0 = bias[col]; b1 = bias[col + 1]; }
#pragma unroll
        for (int mi = 0; mi < 2; mi++) {
            int row = bm + wm * 32 + mi * 16 + (lane >> 2);
            float2 v0 = make_float2(acc[mi][ni][0] + b0, acc[mi][ni][1] + b1);
            float2 v1 = make_float2(acc[mi][ni][2] + b0, acc[mi][ni][3] + b1);
            if (Ch) {
                *(__half2*)(Ch + (size_t)row * N + col) = __floats2half2_rn(v0.x, v0.y);
                *(__half2*)(Ch + (size_t)(row + 8) * N + col) = __floats2half2_rn(v1.x, v1.y);
            } else {
                *(float2*)(Cf + (size_t)row * N + col) = v0;
                *(float2*)(Cf + (size_t)(row + 8) * N + col) = v1;
            }
        }
    }
}

// ============ gate-grouped iou GEMM with fused leaf activation ============
// grid (4, 1170). Each CTA: 128 rows x 64 cols x 3 gates. A tile 128 rows,
// B tile 192 rows (64 per gate). Stage = 320 rows * 80B = 25600B, 4 stages.
#define GSTAGE_B 25600
#define GIOU_SMEM (NSTAGE * GSTAGE_B)

__device__ __forceinline__ void giou_load_stage(uint32_t dst, const __half* A0,
                                                const __half* W, int bn, int k0, int tid) {
#pragma unroll
    for (int i = 0; i < 3; i++) {
        int chunk = tid + i * 512;        // 0..1535, need 1280
        if (chunk < 1280) {
            int r = chunk >> 2, c = chunk & 3;
            const __half* src;
            if (r < 128) {
                src = A0 + (size_t)r * 512 + k0 + c * 8;
            } else {
                int rb = r - 128;
                int gg = rb >> 6, wr = rb & 63;
                src = W + (size_t)(gg * 256 + bn + wr) * 512 + k0 + c * 8;
            }
            cpa16(dst + r * 80 + c * 16, src);
        }
    }
    CP_COMMIT();
}

__global__ __launch_bounds__(512, 1)
void giou_gemm(const __half* __restrict__ A, const __half* __restrict__ W,
               const float* __restrict__ biou, __half* __restrict__ P,
               __half* __restrict__ c16, float* __restrict__ h_all,
               __half* __restrict__ h16) {
    extern __shared__ __align__(128) char smem[];
    uint32_t sb = smem_u32(smem);
    const int tid = threadIdx.x;
    const int warp = tid >> 5;
    const int lane = tid & 31;
    const int wm = warp >> 2;       // 0..3
    const int wn = warp & 3;        // 0..3
    const int bn = blockIdx.x * 64; // gate-local col base
    const int bm = blockIdx.y * 128;
    const int NK = 16;              // K=512

    const __half* A0 = A + (size_t)bm * 512;

#pragma unroll
    for (int s = 0; s < NSTAGE - 1; s++)
        giou_load_stage(sb + s * GSTAGE_B, A0, W, bn, s * 32, tid);

    float acc[2][3][2][4];
#pragma unroll
    for (int mi = 0; mi < 2; mi++)
#pragma unroll
        for (int g = 0; g < 3; g++)
#pragma unroll
            for (int ni = 0; ni < 2; ni++)
#pragma unroll
                for (int r = 0; r < 4; r++) acc[mi][g][ni][r] = 0.f;

    uint32_t aoff[2], boff[3];
#pragma unroll
    for (int mi = 0; mi < 2; mi++)
        aoff[mi] = (uint32_t)((wm * 32 + mi * 16 + (lane & 15)) * 80 + (lane >> 4) * 16);
#pragma unroll
    for (int g = 0; g < 3; g++)
        boff[g] = (uint32_t)(10240 + (g * 64 + wn * 16 + (lane & 15)) * 80 + (lane >> 4) * 16);

    for (int k = 0; k < NK; k++) {
        int kpre = k + NSTAGE - 1;
        if (kpre < NK)
            giou_load_stage(sb + (kpre % NSTAGE) * GSTAGE_B, A0, W, bn, kpre * 32, tid);
        int inflight = ((kpre < NK ? kpre : NK - 1)) - k;
        if (inflight >= 3)      asm volatile("cp.async.wait_group 3;" ::: "memory");
        else if (inflight == 2) asm volatile("cp.async.wait_group 2;" ::: "memory");
        else if (inflight == 1) asm volatile("cp.async.wait_group 1;" ::: "memory");
        else                    asm volatile("cp.async.wait_group 0;" ::: "memory");
        __syncthreads();

        uint32_t st = sb + (k % NSTAGE) * GSTAGE_B;
#pragma unroll
        for (int ks = 0; ks < 2; ks++) {
            uint32_t ko = ks * 32;
            uint32_t ah[2][4], bh[3][4];
#pragma unroll
            for (int mi = 0; mi < 2; mi++) LDSM4(ah[mi], st + aoff[mi] + ko);
#pragma unroll
            for (int g = 0; g < 3; g++) LDSM4(bh[g], st + boff[g] + ko);
#pragma unroll
            for (int mi = 0; mi < 2; mi++)
#pragma unroll
                for (int g = 0; g < 3; g++) {
                    MMAH(acc[mi][g][0], ah[mi], bh[g][0], bh[g][2]);
                    MMAH(acc[mi][g][1], ah[mi], bh[g][1], bh[g][3]);
                }
        }
        __syncthreads();
    }

    // epilogue
    const bool leaf = (blockIdx.y >= 146);
#pragma unroll
    for (int ni = 0; ni < 2; ni++) {
        int col = bn + wn * 16 + ni * 8 + (lane & 3) * 2;   // gate-local col 0..255
        float bi0 = biou[col],       bi1 = biou[col + 1];
        float bo0 = biou[256 + col], bo1 = biou[256 + col + 1];
        float bu0 = biou[512 + col], bu1 = biou[512 + col + 1];
#pragma unroll
        for (int mi = 0; mi < 2; mi++) {
            int row0 = bm + wm * 32 + mi * 16 + (lane >> 2);
#pragma unroll
            for (int rr = 0; rr < 2; rr++) {
                int row = row0 + rr * 8;
                int ro = rr * 2;
                float pi0 = acc[mi][0][ni][ro] + bi0,     pi1 = acc[mi][0][ni][ro + 1] + bi1;
                float po0 = acc[mi][1][ni][ro] + bo0,     po1 = acc[mi][1][ni][ro + 1] + bo1;
                float pu0 = acc[mi][2][ni][ro] + bu0,     pu1 = acc[mi][2][ni][ro + 1] + bu1;
                size_t off = (size_t)row * 256 + col;
                if (leaf) {
                    float i0 = sigf(pi0), i1 = sigf(pi1);
                    float o0 = sigf(po0), o1 = sigf(po1);
                    float u0 = tanhf(pu0), u1 = tanhf(pu1);
                    float c0 = i0 * u0, c1 = i1 * u1;
                    float h0 = o0 * tanhf(c0), h1 = o1 * tanhf(c1);
                    *(__half2*)(c16 + off) = __floats2half2_rn(c0, c1);
                    *(float2*)(h_all + off) = make_float2(h0, h1);
                    *(__half2*)(h16 + off) = __floats2half2_rn(h0, h1);
                } else {
                    *(__half2*)(P + off) = __floats2half2_rn(pi0, pi1);
                    *(__half2*)(P + PLANE + off) = __floats2half2_rn(po0, po1);
                    *(__half2*)(P + 2 * PLANE + off) = __floats2half2_rn(pu0, pu1);
                }
            }
        }
    }
}

// ---------------- weighted child-h sum (reads h16, fp16 out) ----------------
__global__ void prep_level(const __half* __restrict__ h16, const float* __restrict__ prob,
                           __half* __restrict__ hs, int s) {
    int idx = blockIdx.x * blockDim.x + threadIdx.x;  // L*256*256
    int m = idx & 255;
    int b = (idx >> 8) & 255;
    int nl = idx >> 16;
    int n = s + nl;
    int c0 = n * 8 + 1;
    float sum = 0.f;
#pragma unroll
    for (int j = 0; j < 8; j++) {
        float w = prob[n * 585 + c0 + j];
        float hv = __half2float(h16[((long long)(c0 + j) * 256 + b) * 256 + m]);
        sum += w * hv;
    }
    hs[idx] = __float2half(sum);
}

// ---------------- combine: gates + cell update ----------------
__global__ void combine_level(const __half* __restrict__ P, const float* __restrict__ S,
                              const __half* __restrict__ G, const __half* __restrict__ Pfx,
                              const float* __restrict__ bfh, const float* __restrict__ prob,
                              __half* __restrict__ c16, float* __restrict__ h_all,
                              __half* __restrict__ h16, int s) {
    int idx = blockIdx.x * blockDim.x + threadIdx.x;  // L*256*256
    int m = idx & 255;
    int b = (idx >> 8) & 255;
    int nl = idx >> 16;
    int n = s + nl;
    long long prow = (long long)n * 256 + b;
    size_t poff = (size_t)prow * 256 + m;
    const float* sp = S + (long long)(idx >> 8) * 768;
    float i = sigf(__half2float(P[poff]) + sp[m]);
    float o = sigf(__half2float(P[PLANE + poff]) + sp[256 + m]);
    float u = tanhf(__half2float(P[2 * PLANE + poff]) + sp[512 + m]);
    float fx = __half2float(Pfx[poff]) + bfh[m];
    float c = i * u;
    int c0 = n * 8 + 1;
    int gbase = (n - s) * 8;
#pragma unroll
    for (int j = 0; j < 8; j++) {
        float g = __half2float(G[((long long)((gbase + j) * 256 + b)) * 256 + m]);
        float w = prob[n * 585 + c0 + j];
        float f = sigf(w * g + fx);
        float cc = __half2float(c16[((long long)(c0 + j) * 256 + b) * 256 + m]);
        c += f * (w * cc);
    }
    float h = o * tanhf(c);
    c16[poff] = __float2half(c);
    h_all[poff] = h;
    h16[poff] = __float2half(h);
}

// ---------------- launch ----------------
extern "C" void kernel_launch(void* const* d_in, const int* in_sizes, int n_in,
                              void* d_out, int out_size) {
    const float* inputs = (const float*)d_in[0];
    const float* prob = (const float*)d_in[1];
    const float* Wioux = (const float*)d_in[2];
    const float* bioux = (const float*)d_in[3];
    const float* Wiouh = (const float*)d_in[4];
    const float* biouh = (const float*)d_in[5];
    const float* Wfx = (const float*)d_in[6];
    const float* bfx = (const float*)d_in[7];
    const float* Wfh = (const float*)d_in[8];
    const float* bfh = (const float*)d_in[9];
    float* h_all = (float*)d_out;

    float *Sb, *biou;
    __half *P, *Pfx, *c16, *Gb, *Ah, *Wiou16, *Wfx16, *Whh, *Wf16, *HS, *h16;
    cudaGetSymbolAddress((void**)&P, g_P);
    cudaGetSymbolAddress((void**)&Pfx, g_Pfx);
    cudaGetSymbolAddress((void**)&c16, g_c16);
    cudaGetSymbolAddress((void**)&Sb, g_S);
    cudaGetSymbolAddress((void**)&Gb, g_G);
    cudaGetSymbolAddress((void**)&biou, g_biou);
    cudaGetSymbolAddress((void**)&Ah, g_Ah);
    cudaGetSymbolAddress((void**)&Wiou16, g_Wiou);
    cudaGetSymbolAddress((void**)&Wfx16, g_Wfx16);
    cudaGetSymbolAddress((void**)&Whh, g_Whh);
    cudaGetSymbolAddress((void**)&Wf16, g_Wf16);
    cudaGetSymbolAddress((void**)&HS, g_HS);
    cudaGetSymbolAddress((void**)&h16, g_h16);

    cudaFuncSetAttribute(tgemm, cudaFuncAttributeMaxDynamicSharedMemorySize, GEMM_SMEM);
    cudaFuncSetAttribute(giou_gemm, cudaFuncAttributeMaxDynamicSharedMemorySize, GIOU_SMEM);

    // conversions / packing
    conv_half<<<(int)((size_t)ROWS * 512 / 4 / 256), 256>>>(inputs, Ah, (long long)ROWS * 512 / 4);
    pack_wiou<<<(768 * 512) / 256, 256>>>(Wioux, bioux, biouh);
    conv_half<<<128, 256>>>(Wfx, Wfx16, 256 * 512 / 4);
    conv_half<<<192, 256>>>(Wiouh, Whh, 768 * 256 / 4);
    conv_half<<<64, 256>>>(Wfh, Wf16, 256 * 256 / 4);

    // gate-grouped iou projection + fused leaf activation
    giou_gemm<<<dim3(4, ROWS / 128), 512, GIOU_SMEM>>>(Ah, Wiou16, biou, P, c16, h_all, h16);
    // P_fx = X[internal] @ Wfx^T + bfx  (18688 x 256 x 512) -> fp16
    tgemm<<<dim3(2, IROWS / 128), 512, GEMM_SMEM>>>(Ah, Wfx16, bfx, nullptr, Pfx,
                                                    IROWS, 256, 512);

    // internal levels bottom-up
    const int starts[3] = {9, 1, 0};
    const int sizes[3] = {64, 8, 1};
    for (int l = 0; l < 3; l++) {
        int s = starts[l], L = sizes[l];
        int childRows = L * 8 * 256;
        // G = h16[children] @ Wfh^T  -> fp16
        tgemm<<<dim3(2, childRows / 128), 512, GEMM_SMEM>>>(
            h16 + (size_t)(s * 8 + 1) * 256 * 256, Wf16, nullptr, nullptr, Gb,
            childRows, 256, 256);
        // hsum (from h16)
        prep_level<<<(L * 256 * 256) / 256, 256>>>(h16, prob, HS, s);
        // S = hsum @ Wiouh^T  -> fp32
        tgemm<<<dim3(6, (L * 256) / 128), 512, GEMM_SMEM>>>(HS, Whh, nullptr, Sb, nullptr,
                                                            L * 256, 768, 256);
        combine_level<<<(L * 256 * 256) / 256, 256>>>(P, Sb, Gb, Pfx, bfh, prob,
                                                      c16, h_all, h16, s);
    }
}